// round 4
// baseline (speedup 1.0000x reference)
#include <cuda_runtime.h>
#include <math.h>
#include <stdint.h>

#define BATCH 8
#define SEQ 1370
#define DIM 1024
#define HEADS 16
#define HDIM 64
#define MROWS (BATCH * SEQ)   // 10960

// Scratch (allocation-free: device globals)
__device__ float g_q[BATCH * HEADS * SEQ * HDIM];   // [B,H,S,Dh]
__device__ float g_k[BATCH * HEADS * SEQ * HDIM];
__device__ float g_v[BATCH * HEADS * SEQ * HDIM];
__device__ float g_ctx[BATCH * SEQ * DIM];          // [B,S,D]

__device__ __forceinline__ float to_tf32(float x) {
    float r; asm("cvt.rna.tf32.f32 %0, %1;" : "=f"(r) : "f"(x)); return r;
}
__device__ __forceinline__ unsigned fu(float x) { return __float_as_uint(x); }

__device__ __forceinline__ void mma_tf32(float c[4],
    unsigned a0, unsigned a1, unsigned a2, unsigned a3,
    unsigned b0, unsigned b1)
{
    asm volatile(
        "mma.sync.aligned.m16n8k8.row.col.f32.tf32.tf32.f32 "
        "{%0,%1,%2,%3}, {%4,%5,%6,%7}, {%8,%9}, {%0,%1,%2,%3};"
        : "+f"(c[0]), "+f"(c[1]), "+f"(c[2]), "+f"(c[3])
        : "r"(a0), "r"(a1), "r"(a2), "r"(a3), "r"(b0), "r"(b1));
}

// ---------------------------------------------------------------------------
// TF32 GEMM: C[M,1024] = A[M,1024] @ W[1024,1024] + bias
// CTA tile 256x128, BK=16, 8 warps (4 row-groups x 2 col-groups),
// warp tile 64x64 (mt=4 x nt=8 m16n8k8 MMAs).
// csel 0/1/2 -> g_q/g_k/g_v ([B,H,S,Dh]); 3 -> Cext [M,N]. asel 1 -> g_ctx.
// ---------------------------------------------------------------------------
#define AST 20
#define BST 136

__device__ __forceinline__ void store_pair(int csel, float* __restrict__ Cext,
                                           int m, int n, float v0, float v1)
{
    if (m >= MROWS) return;
    if (csel <= 2) {
        float* dst = (csel == 0) ? g_q : (csel == 1) ? g_k : g_v;
        int b = m / SEQ;
        int s = m - b * SEQ;
        int h = n >> 6;
        int d = n & 63;
        *(float2*)&dst[(((size_t)(b * HEADS + h)) * SEQ + s) * HDIM + d] =
            make_float2(v0, v1);
    } else {
        *(float2*)&Cext[(size_t)m * DIM + n] = make_float2(v0, v1);
    }
}

__global__ __launch_bounds__(256) void gemm_tf32(
    const float* __restrict__ Aext, const float* __restrict__ W,
    const float* __restrict__ bias, float* __restrict__ Cext,
    int asel, int csel)
{
    __shared__ float As[256 * AST];
    __shared__ float Bs[16 * BST];

    const float* A = (asel == 1) ? g_ctx : Aext;

    int tid = threadIdx.x;
    int wid = tid >> 5, lane = tid & 31;
    int wm = wid >> 1, wn = wid & 1;   // 4 row groups x 2 col groups
    int lr = lane >> 2, lc = lane & 3;
    int m0 = blockIdx.x * 256, n0 = blockIdx.y * 128;

    float c[4][8][4];
#pragma unroll
    for (int mt = 0; mt < 4; mt++)
#pragma unroll
        for (int nt = 0; nt < 8; nt++)
#pragma unroll
            for (int i = 0; i < 4; i++) c[mt][nt][i] = 0.f;

    // A loader: 4 float4/thread. idx = tid + i*256: row = idx>>2, koff = (idx&3)*4
    int arow[4]; int akoff[4]; bool aval[4];
#pragma unroll
    for (int i = 0; i < 4; i++) {
        int idx = tid + i * 256;
        arow[i] = idx >> 2;
        akoff[i] = (idx & 3) * 4;
        aval[i] = (m0 + arow[i]) < MROWS;
    }
    // B loader: 2 float4/thread. idx = tid + i*256: row = idx>>5, noff = (idx&31)*4
    int brow[2]; int bnoff[2];
#pragma unroll
    for (int i = 0; i < 2; i++) {
        int idx = tid + i * 256;
        brow[i] = idx >> 5;
        bnoff[i] = (idx & 31) * 4;
    }

    const float4 z4 = make_float4(0.f, 0.f, 0.f, 0.f);
    float4 ra[4], rb[2];
#pragma unroll
    for (int i = 0; i < 4; i++)
        ra[i] = aval[i] ? *(const float4*)(A + (size_t)(m0 + arow[i]) * DIM + akoff[i]) : z4;
#pragma unroll
    for (int i = 0; i < 2; i++)
        rb[i] = *(const float4*)(W + (size_t)brow[i] * DIM + n0 + bnoff[i]);

    for (int t = 0; t < 64; t++) {
        __syncthreads();
#pragma unroll
        for (int i = 0; i < 4; i++)
            *(float4*)&As[arow[i] * AST + akoff[i]] = make_float4(
                to_tf32(ra[i].x), to_tf32(ra[i].y), to_tf32(ra[i].z), to_tf32(ra[i].w));
#pragma unroll
        for (int i = 0; i < 2; i++)
            *(float4*)&Bs[brow[i] * BST + bnoff[i]] = make_float4(
                to_tf32(rb[i].x), to_tf32(rb[i].y), to_tf32(rb[i].z), to_tf32(rb[i].w));
        __syncthreads();

        if (t < 63) {
            int k0 = (t + 1) * 16;
#pragma unroll
            for (int i = 0; i < 4; i++)
                ra[i] = aval[i] ? *(const float4*)(A + (size_t)(m0 + arow[i]) * DIM + k0 + akoff[i]) : z4;
#pragma unroll
            for (int i = 0; i < 2; i++)
                rb[i] = *(const float4*)(W + (size_t)(k0 + brow[i]) * DIM + n0 + bnoff[i]);
        }

#pragma unroll
        for (int ks = 0; ks < 2; ks++) {
            int kk = ks * 8;
            unsigned bf[8][2];
#pragma unroll
            for (int nt = 0; nt < 8; nt++) {
                int col = wn * 64 + nt * 8 + lr;
                bf[nt][0] = fu(Bs[(kk + lc) * BST + col]);
                bf[nt][1] = fu(Bs[(kk + lc + 4) * BST + col]);
            }
#pragma unroll
            for (int mt = 0; mt < 4; mt++) {
                int ar = wm * 64 + mt * 16 + lr;
                unsigned a0 = fu(As[ar * AST + kk + lc]);
                unsigned a1 = fu(As[(ar + 8) * AST + kk + lc]);
                unsigned a2 = fu(As[ar * AST + kk + lc + 4]);
                unsigned a3 = fu(As[(ar + 8) * AST + kk + lc + 4]);
#pragma unroll
                for (int nt = 0; nt < 8; nt++)
                    mma_tf32(c[mt][nt], a0, a1, a2, a3, bf[nt][0], bf[nt][1]);
            }
        }
    }

    // Epilogue
#pragma unroll
    for (int mt = 0; mt < 4; mt++) {
        int r0 = m0 + wm * 64 + mt * 16 + lr;
        int r1 = r0 + 8;
#pragma unroll
        for (int nt = 0; nt < 8; nt++) {
            int n = n0 + wn * 64 + nt * 8 + lc * 2;
            float b0v = bias[n], b1v = bias[n + 1];
            store_pair(csel, Cext, r0, n, c[mt][nt][0] + b0v, c[mt][nt][1] + b1v);
            store_pair(csel, Cext, r1, n, c[mt][nt][2] + b0v, c[mt][nt][3] + b1v);
        }
    }
}

// ---------------------------------------------------------------------------
// TF32 flash attention, register-resident.
// CTA: 128 q-rows, 8 warps; warp owns 16 full rows (warp tile 16x64).
// Q fragments hoisted to registers (loaded once from gmem).
// Softmax fully in registers (quad shuffles). P transposed C-frag -> A-frag
// via warp shuffles; no P smem, no softmax smem pass. Smem = K,V tiles only.
// ---------------------------------------------------------------------------
#define KST 68   // Ks stride (conflict-free b-frag loads)
#define VST 72   // Vs stride (conflict-free b-frag loads)

__global__ __launch_bounds__(256) void attn_tf32()
{
    __shared__ float Ks[64 * KST];
    __shared__ float Vs[64 * VST];

    int tid = threadIdx.x;
    int w = tid >> 5, lane = tid & 31;
    int lr = lane >> 2, lc = lane & 3;

    int bh = blockIdx.y;
    int b = bh >> 4;
    int h = bh & 15;
    int q0 = blockIdx.x * 128;

    const float* Qg = g_q + ((size_t)(b * HEADS + h)) * SEQ * HDIM;
    const float* Kg = g_k + ((size_t)(b * HEADS + h)) * SEQ * HDIM;
    const float* Vg = g_v + ((size_t)(b * HEADS + h)) * SEQ * HDIM;

    int r0 = q0 + w * 16 + lr;
    int r1 = r0 + 8;

    // Hoist Q fragments (pre-scaled by 1/sqrt(64)=0.125, tf32)
    unsigned qf[8][4];
#pragma unroll
    for (int ks = 0; ks < 8; ks++) {
        int k = ks * 8 + lc;
        float v0 = (r0 < SEQ) ? Qg[(size_t)r0 * HDIM + k] : 0.f;
        float v1 = (r1 < SEQ) ? Qg[(size_t)r1 * HDIM + k] : 0.f;
        float v2 = (r0 < SEQ) ? Qg[(size_t)r0 * HDIM + k + 4] : 0.f;
        float v3 = (r1 < SEQ) ? Qg[(size_t)r1 * HDIM + k + 4] : 0.f;
        qf[ks][0] = fu(to_tf32(v0 * 0.125f));
        qf[ks][1] = fu(to_tf32(v1 * 0.125f));
        qf[ks][2] = fu(to_tf32(v2 * 0.125f));
        qf[ks][3] = fu(to_tf32(v3 * 0.125f));
    }

    float o[8][4];
#pragma unroll
    for (int od = 0; od < 8; od++)
#pragma unroll
        for (int i = 0; i < 4; i++) o[od][i] = 0.f;
    float m0v = -INFINITY, m1v = -INFINITY, l0 = 0.f, l1 = 0.f;

    const float4 z4 = make_float4(0.f, 0.f, 0.f, 0.f);

    for (int k0 = 0; k0 < SEQ; k0 += 64) {
        __syncthreads();  // previous PV done reading Ks/Vs
        // Load K/V tile (tf32-rounded)
        for (int e = tid; e < 1024; e += 256) {
            int r = e >> 4;
            int d4 = (e & 15) * 4;
            float4 kv = z4, vv = z4;
            if (k0 + r < SEQ) {
                kv = *(const float4*)(Kg + (size_t)(k0 + r) * HDIM + d4);
                vv = *(const float4*)(Vg + (size_t)(k0 + r) * HDIM + d4);
            }
            *(float4*)&Ks[r * KST + d4] = make_float4(
                to_tf32(kv.x), to_tf32(kv.y), to_tf32(kv.z), to_tf32(kv.w));
            *(float4*)&Vs[r * VST + d4] = make_float4(
                to_tf32(vv.x), to_tf32(vv.y), to_tf32(vv.z), to_tf32(vv.w));
        }
        __syncthreads();

        // S = (Q*scale) @ K^T : warp tile 16x64
        float s[8][4];
#pragma unroll
        for (int nt = 0; nt < 8; nt++)
#pragma unroll
            for (int i = 0; i < 4; i++) s[nt][i] = 0.f;

#pragma unroll
        for (int ks = 0; ks < 8; ks++) {
            int kk = ks * 8;
#pragma unroll
            for (int nt = 0; nt < 8; nt++) {
                unsigned b0 = fu(Ks[(nt * 8 + lr) * KST + kk + lc]);
                unsigned b1 = fu(Ks[(nt * 8 + lr) * KST + kk + lc + 4]);
                mma_tf32(s[nt], qf[ks][0], qf[ks][1], qf[ks][2], qf[ks][3], b0, b1);
            }
        }

        // Mask + row max (fully in registers; quad shuffles complete the row)
        float rmax0 = -INFINITY, rmax1 = -INFINITY;
#pragma unroll
        for (int nt = 0; nt < 8; nt++) {
#pragma unroll
            for (int e = 0; e < 2; e++) {
                int col = k0 + nt * 8 + 2 * lc + e;
                if (col >= SEQ) { s[nt][e] = -INFINITY; s[nt][2 + e] = -INFINITY; }
                rmax0 = fmaxf(rmax0, s[nt][e]);
                rmax1 = fmaxf(rmax1, s[nt][2 + e]);
            }
        }
        rmax0 = fmaxf(rmax0, __shfl_xor_sync(0xffffffffu, rmax0, 1));
        rmax0 = fmaxf(rmax0, __shfl_xor_sync(0xffffffffu, rmax0, 2));
        rmax1 = fmaxf(rmax1, __shfl_xor_sync(0xffffffffu, rmax1, 1));
        rmax1 = fmaxf(rmax1, __shfl_xor_sync(0xffffffffu, rmax1, 2));

        float mn0 = fmaxf(m0v, rmax0);
        float mn1 = fmaxf(m1v, rmax1);
        float alpha0 = __expf(m0v - mn0);
        float alpha1 = __expf(m1v - mn1);
        m0v = mn0; m1v = mn1;

        float sum0 = 0.f, sum1 = 0.f;
#pragma unroll
        for (int nt = 0; nt < 8; nt++) {
#pragma unroll
            for (int e = 0; e < 2; e++) {
                float p0 = __expf(s[nt][e] - mn0);
                float p1 = __expf(s[nt][2 + e] - mn1);
                sum0 += p0; sum1 += p1;
                s[nt][e] = to_tf32(p0);
                s[nt][2 + e] = to_tf32(p1);
            }
        }
        sum0 += __shfl_xor_sync(0xffffffffu, sum0, 1);
        sum0 += __shfl_xor_sync(0xffffffffu, sum0, 2);
        sum1 += __shfl_xor_sync(0xffffffffu, sum1, 1);
        sum1 += __shfl_xor_sync(0xffffffffu, sum1, 2);
        l0 = l0 * alpha0 + sum0;
        l1 = l1 * alpha1 + sum1;

#pragma unroll
        for (int od = 0; od < 8; od++) {
            o[od][0] *= alpha0; o[od][1] *= alpha0;
            o[od][2] *= alpha1; o[od][3] *= alpha1;
        }

        // PV: transpose P C-frag -> A-frag via shuffles, MMA against Vs
        int srcA = lr * 4 + (lc >> 1);
        int srcB = srcA + 2;
        bool odd = lc & 1;
#pragma unroll
        for (int kb = 0; kb < 8; kb++) {
            float s0 = __shfl_sync(0xffffffffu, s[kb][0], srcA);
            float s1 = __shfl_sync(0xffffffffu, s[kb][1], srcA);
            float s2 = __shfl_sync(0xffffffffu, s[kb][2], srcA);
            float s3 = __shfl_sync(0xffffffffu, s[kb][3], srcA);
            float t0 = __shfl_sync(0xffffffffu, s[kb][0], srcB);
            float t1 = __shfl_sync(0xffffffffu, s[kb][1], srcB);
            float t2 = __shfl_sync(0xffffffffu, s[kb][2], srcB);
            float t3 = __shfl_sync(0xffffffffu, s[kb][3], srcB);
            unsigned a0 = fu(odd ? s1 : s0);
            unsigned a1 = fu(odd ? s3 : s2);
            unsigned a2 = fu(odd ? t1 : t0);
            unsigned a3 = fu(odd ? t3 : t2);
#pragma unroll
            for (int od = 0; od < 8; od++) {
                unsigned b0 = fu(Vs[(kb * 8 + lc) * VST + od * 8 + lr]);
                unsigned b1 = fu(Vs[(kb * 8 + lc + 4) * VST + od * 8 + lr]);
                mma_tf32(o[od], a0, a1, a2, a3, b0, b1);
            }
        }
    }

    // Epilogue: normalize, write [B,S,D]
    float inv0 = 1.f / l0;
    float inv1 = 1.f / l1;
#pragma unroll
    for (int od = 0; od < 8; od++) {
        int col = h * HDIM + od * 8 + lc * 2;
        if (r0 < SEQ)
            *(float2*)&g_ctx[((size_t)(b * SEQ + r0)) * DIM + col] =
                make_float2(o[od][0] * inv0, o[od][1] * inv0);
        if (r1 < SEQ)
            *(float2*)&g_ctx[((size_t)(b * SEQ + r1)) * DIM + col] =
                make_float2(o[od][2] * inv1, o[od][3] * inv1);
    }
}

// ---------------------------------------------------------------------------
extern "C" void kernel_launch(void* const* d_in, const int* in_sizes, int n_in,
                              void* d_out, int out_size)
{
    const float* x  = (const float*)d_in[0];
    const float* Wq = (const float*)d_in[1];
    const float* bq = (const float*)d_in[2];
    const float* Wk = (const float*)d_in[3];
    const float* bk = (const float*)d_in[4];
    const float* Wv = (const float*)d_in[5];
    const float* bv = (const float*)d_in[6];
    const float* Wo = (const float*)d_in[7];
    const float* bo = (const float*)d_in[8];
    float* out = (float*)d_out;

    dim3 gemmGrid((MROWS + 255) / 256, DIM / 128);  // 43 x 8

    gemm_tf32<<<gemmGrid, 256>>>(x, Wq, bq, nullptr, 0, 0);
    gemm_tf32<<<gemmGrid, 256>>>(x, Wk, bk, nullptr, 0, 1);
    gemm_tf32<<<gemmGrid, 256>>>(x, Wv, bv, nullptr, 0, 2);

    dim3 attnGrid((SEQ + 127) / 128, BATCH * HEADS);  // 11 x 128
    attn_tf32<<<attnGrid, 256>>>();

    gemm_tf32<<<gemmGrid, 256>>>(nullptr, Wo, bo, out, 1, 3);
}

// round 5
// speedup vs baseline: 1.3167x; 1.3167x over previous
#include <cuda_runtime.h>
#include <math.h>
#include <stdint.h>

#define BATCH 8
#define SEQ 1370
#define DIM 1024
#define HEADS 16
#define HDIM 64
#define MROWS (BATCH * SEQ)   // 10960

// Scratch (allocation-free: device globals)
__device__ float g_q[BATCH * HEADS * SEQ * HDIM];   // [B,H,S,Dh]
__device__ float g_k[BATCH * HEADS * SEQ * HDIM];
__device__ float g_v[BATCH * HEADS * SEQ * HDIM];
__device__ float g_ctx[BATCH * SEQ * DIM];          // [B,S,D]

__device__ __forceinline__ float to_tf32(float x) {
    float r; asm("cvt.rna.tf32.f32 %0, %1;" : "=f"(r) : "f"(x)); return r;
}
__device__ __forceinline__ unsigned fu(float x) { return __float_as_uint(x); }

__device__ __forceinline__ void mma_tf32(float c[4],
    unsigned a0, unsigned a1, unsigned a2, unsigned a3,
    unsigned b0, unsigned b1)
{
    asm volatile(
        "mma.sync.aligned.m16n8k8.row.col.f32.tf32.tf32.f32 "
        "{%0,%1,%2,%3}, {%4,%5,%6,%7}, {%8,%9}, {%0,%1,%2,%3};"
        : "+f"(c[0]), "+f"(c[1]), "+f"(c[2]), "+f"(c[3])
        : "r"(a0), "r"(a1), "r"(a2), "r"(a3), "r"(b0), "r"(b1));
}

// ---------------------------------------------------------------------------
// TF32 GEMM (R3 proven config): C[M,1024] = A[M,1024] @ W[1024,1024] + bias
// 128x128 tile, BK=16, 8 warps (2x4), warp tile 64x32, m16n8k8 tf32 MMA.
// csel 0/1/2 -> g_q/g_k/g_v ([B,H,S,Dh]); 3 -> Cext [M,N]. asel 1 -> g_ctx.
// ---------------------------------------------------------------------------
__device__ __forceinline__ void store_pair(int csel, float* __restrict__ Cext,
                                           int m, int n, float v0, float v1)
{
    if (m >= MROWS) return;
    if (csel <= 2) {
        float* dst = (csel == 0) ? g_q : (csel == 1) ? g_k : g_v;
        int b = m / SEQ;
        int s = m - b * SEQ;
        int h = n >> 6;
        int d = n & 63;
        *(float2*)&dst[(((size_t)(b * HEADS + h)) * SEQ + s) * HDIM + d] =
            make_float2(v0, v1);
    } else {
        *(float2*)&Cext[(size_t)m * DIM + n] = make_float2(v0, v1);
    }
}

__global__ __launch_bounds__(256) void gemm_tf32(
    const float* __restrict__ Aext, const float* __restrict__ W,
    const float* __restrict__ bias, float* __restrict__ Cext,
    int asel, int csel)
{
    __shared__ float As[128][20];
    __shared__ float Bs[16][136];

    const float* A = (asel == 1) ? g_ctx : Aext;

    int tid = threadIdx.x;
    int wid = tid >> 5, lane = tid & 31;
    int wm = wid & 1, wn = wid >> 1;
    int lr = lane >> 2, lc = lane & 3;
    int m0 = blockIdx.x * 128, n0 = blockIdx.y * 128;

    float c[4][4][4];
#pragma unroll
    for (int mt = 0; mt < 4; mt++)
#pragma unroll
        for (int nt = 0; nt < 4; nt++)
#pragma unroll
            for (int i = 0; i < 4; i++) c[mt][nt][i] = 0.f;

    int am = tid >> 1, ak = (tid & 1) * 8;
    bool aval = (m0 + am) < MROWS;
    const float* Ap = A + (size_t)(m0 + am) * DIM + ak;
    int bk = tid >> 4, bn = (tid & 15) * 4;
    const float* Bp = W + (size_t)bk * DIM + n0 + bn;

    const float4 z4 = make_float4(0.f, 0.f, 0.f, 0.f);
    float4 ra0, ra1, rb0, rb1;
    ra0 = aval ? *(const float4*)(Ap)     : z4;
    ra1 = aval ? *(const float4*)(Ap + 4) : z4;
    rb0 = *(const float4*)(Bp);
    rb1 = *(const float4*)(Bp + 64);

    for (int t = 0; t < 64; t++) {
        __syncthreads();
        *(float4*)&As[am][ak] =
            make_float4(to_tf32(ra0.x), to_tf32(ra0.y), to_tf32(ra0.z), to_tf32(ra0.w));
        *(float4*)&As[am][ak + 4] =
            make_float4(to_tf32(ra1.x), to_tf32(ra1.y), to_tf32(ra1.z), to_tf32(ra1.w));
        *(float4*)&Bs[bk][bn] =
            make_float4(to_tf32(rb0.x), to_tf32(rb0.y), to_tf32(rb0.z), to_tf32(rb0.w));
        *(float4*)&Bs[bk][bn + 64] =
            make_float4(to_tf32(rb1.x), to_tf32(rb1.y), to_tf32(rb1.z), to_tf32(rb1.w));
        __syncthreads();

        if (t < 63) {
            const float* Ap2 = Ap + (t + 1) * 16;
            ra0 = aval ? *(const float4*)(Ap2)     : z4;
            ra1 = aval ? *(const float4*)(Ap2 + 4) : z4;
            const float* Bp2 = Bp + (size_t)(t + 1) * 16 * DIM;
            rb0 = *(const float4*)(Bp2);
            rb1 = *(const float4*)(Bp2 + 64);
        }

#pragma unroll
        for (int ks = 0; ks < 2; ks++) {
            int kk = ks * 8;
            unsigned bf[4][2];
#pragma unroll
            for (int nt = 0; nt < 4; nt++) {
                int col = wn * 32 + nt * 8 + lr;
                bf[nt][0] = fu(Bs[kk + lc][col]);
                bf[nt][1] = fu(Bs[kk + lc + 4][col]);
            }
#pragma unroll
            for (int mt = 0; mt < 4; mt++) {
                int ar = wm * 64 + mt * 16 + lr;
                unsigned a0 = fu(As[ar][kk + lc]);
                unsigned a1 = fu(As[ar + 8][kk + lc]);
                unsigned a2 = fu(As[ar][kk + lc + 4]);
                unsigned a3 = fu(As[ar + 8][kk + lc + 4]);
#pragma unroll
                for (int nt = 0; nt < 4; nt++)
                    mma_tf32(c[mt][nt], a0, a1, a2, a3, bf[nt][0], bf[nt][1]);
            }
        }
    }

#pragma unroll
    for (int mt = 0; mt < 4; mt++) {
        int r0 = m0 + wm * 64 + mt * 16 + lr;
        int r1 = r0 + 8;
#pragma unroll
        for (int nt = 0; nt < 4; nt++) {
            int n = n0 + wn * 32 + nt * 8 + lc * 2;
            float b0v = bias[n], b1v = bias[n + 1];
            store_pair(csel, Cext, r0, n, c[mt][nt][0] + b0v, c[mt][nt][1] + b1v);
            store_pair(csel, Cext, r1, n, c[mt][nt][2] + b0v, c[mt][nt][3] + b1v);
        }
    }
}

// ---------------------------------------------------------------------------
// TF32 flash attention: 64 q-rows/CTA, 8 warps (wm=0..3 row groups x wn=0..1
// k-col groups). Warp S-tile 16x32. Softmax in registers with tiny cross-warp
// smem exchange. P transposed via warp shuffles (no P smem). Each warp keeps
// a PARTIAL O (its 32 k-cols); halves summed in smem at epilogue.
// ---------------------------------------------------------------------------
#define QST 68
#define KST 68
#define VST 72

__global__ __launch_bounds__(256) void attn_tf32()
{
    extern __shared__ float sm[];
    float* Qs   = sm;                  // [64][68] pre-scaled tf32
    float* Ks   = Qs + 64 * QST;       // [64][68]
    float* Vs   = Ks + 64 * KST;       // [64][72]
    float* pmax = Vs + 64 * VST;       // [2][64]
    float* psum = pmax + 128;          // [2][64]

    int tid = threadIdx.x;
    int wid = tid >> 5, lane = tid & 31;
    int wm = wid & 3;      // row group (16 rows)
    int wn = wid >> 2;     // k-col group (32 cols)
    int lr = lane >> 2, lc = lane & 3;

    int bh = blockIdx.y;
    int b = bh >> 4;
    int h = bh & 15;
    int q0 = blockIdx.x * 64;

    const float* Qg = g_q + ((size_t)(b * HEADS + h)) * SEQ * HDIM;
    const float* Kg = g_k + ((size_t)(b * HEADS + h)) * SEQ * HDIM;
    const float* Vg = g_v + ((size_t)(b * HEADS + h)) * SEQ * HDIM;

    const float4 z4 = make_float4(0.f, 0.f, 0.f, 0.f);

    // Load Q tile (scaled by 0.125, tf32)
    for (int e = tid; e < 1024; e += 256) {
        int r = e >> 4;
        int d4 = (e & 15) * 4;
        float4 v = (q0 + r < SEQ) ? *(const float4*)(Qg + (size_t)(q0 + r) * HDIM + d4) : z4;
        *(float4*)&Qs[r * QST + d4] = make_float4(
            to_tf32(v.x * 0.125f), to_tf32(v.y * 0.125f),
            to_tf32(v.z * 0.125f), to_tf32(v.w * 0.125f));
    }

    float o[8][4];   // partial O: 16 rows x 64 Dh cols, over this warp's k-cols
#pragma unroll
    for (int od = 0; od < 8; od++)
#pragma unroll
        for (int i = 0; i < 4; i++) o[od][i] = 0.f;
    float m0v = -INFINITY, m1v = -INFINITY, l0 = 0.f, l1 = 0.f;

    int row0 = wm * 16 + lr;   // local row ids
    int row1 = row0 + 8;

    for (int k0 = 0; k0 < SEQ; k0 += 64) {
        __syncthreads();  // prev PV done reading Vs; prev psum reads done
        for (int e = tid; e < 1024; e += 256) {
            int r = e >> 4;
            int d4 = (e & 15) * 4;
            float4 kv = z4, vv = z4;
            if (k0 + r < SEQ) {
                kv = *(const float4*)(Kg + (size_t)(k0 + r) * HDIM + d4);
                vv = *(const float4*)(Vg + (size_t)(k0 + r) * HDIM + d4);
            }
            *(float4*)&Ks[r * KST + d4] = make_float4(
                to_tf32(kv.x), to_tf32(kv.y), to_tf32(kv.z), to_tf32(kv.w));
            *(float4*)&Vs[r * VST + d4] = make_float4(
                to_tf32(vv.x), to_tf32(vv.y), to_tf32(vv.z), to_tf32(vv.w));
        }
        __syncthreads();

        // S(16x32) = Q @ K^T over this warp's k-cols
        float s[4][4];
#pragma unroll
        for (int nt = 0; nt < 4; nt++)
#pragma unroll
            for (int i = 0; i < 4; i++) s[nt][i] = 0.f;

#pragma unroll
        for (int ks = 0; ks < 8; ks++) {
            int kk = ks * 8;
            int qr = wm * 16 + lr;
            unsigned a0 = fu(Qs[qr * QST + kk + lc]);
            unsigned a1 = fu(Qs[(qr + 8) * QST + kk + lc]);
            unsigned a2 = fu(Qs[qr * QST + kk + lc + 4]);
            unsigned a3 = fu(Qs[(qr + 8) * QST + kk + lc + 4]);
#pragma unroll
            for (int nt = 0; nt < 4; nt++) {
                int krow = wn * 32 + nt * 8 + lr;
                unsigned b0 = fu(Ks[krow * KST + kk + lc]);
                unsigned b1 = fu(Ks[krow * KST + kk + lc + 4]);
                mma_tf32(s[nt], a0, a1, a2, a3, b0, b1);
            }
        }

        // Mask + warp-local row max (quad shuffles)
        float rmax0 = -INFINITY, rmax1 = -INFINITY;
#pragma unroll
        for (int nt = 0; nt < 4; nt++) {
#pragma unroll
            for (int e = 0; e < 2; e++) {
                int col = k0 + wn * 32 + nt * 8 + 2 * lc + e;
                if (col >= SEQ) { s[nt][e] = -INFINITY; s[nt][2 + e] = -INFINITY; }
                rmax0 = fmaxf(rmax0, s[nt][e]);
                rmax1 = fmaxf(rmax1, s[nt][2 + e]);
            }
        }
        rmax0 = fmaxf(rmax0, __shfl_xor_sync(0xffffffffu, rmax0, 1));
        rmax0 = fmaxf(rmax0, __shfl_xor_sync(0xffffffffu, rmax0, 2));
        rmax1 = fmaxf(rmax1, __shfl_xor_sync(0xffffffffu, rmax1, 1));
        rmax1 = fmaxf(rmax1, __shfl_xor_sync(0xffffffffu, rmax1, 2));

        // Cross-warp max exchange
        if (lc == 0) {
            pmax[wn * 64 + row0] = rmax0;
            pmax[wn * 64 + row1] = rmax1;
        }
        __syncthreads();
        float gmax0 = fmaxf(pmax[row0], pmax[64 + row0]);
        float gmax1 = fmaxf(pmax[row1], pmax[64 + row1]);

        float mn0 = fmaxf(m0v, gmax0);
        float mn1 = fmaxf(m1v, gmax1);
        float alpha0 = __expf(m0v - mn0);
        float alpha1 = __expf(m1v - mn1);
        m0v = mn0; m1v = mn1;

        float sum0 = 0.f, sum1 = 0.f;
#pragma unroll
        for (int nt = 0; nt < 4; nt++) {
#pragma unroll
            for (int e = 0; e < 2; e++) {
                float p0 = __expf(s[nt][e] - mn0);
                float p1 = __expf(s[nt][2 + e] - mn1);
                sum0 += p0; sum1 += p1;
                s[nt][e] = to_tf32(p0);
                s[nt][2 + e] = to_tf32(p1);
            }
        }
        sum0 += __shfl_xor_sync(0xffffffffu, sum0, 1);
        sum0 += __shfl_xor_sync(0xffffffffu, sum0, 2);
        sum1 += __shfl_xor_sync(0xffffffffu, sum1, 1);
        sum1 += __shfl_xor_sync(0xffffffffu, sum1, 2);

        if (lc == 0) {
            psum[wn * 64 + row0] = sum0;
            psum[wn * 64 + row1] = sum1;
        }
        __syncthreads();
        float gsum0 = psum[row0] + psum[64 + row0];
        float gsum1 = psum[row1] + psum[64 + row1];
        l0 = l0 * alpha0 + gsum0;
        l1 = l1 * alpha1 + gsum1;

#pragma unroll
        for (int od = 0; od < 8; od++) {
            o[od][0] *= alpha0; o[od][1] *= alpha0;
            o[od][2] *= alpha1; o[od][3] *= alpha1;
        }

        // PV over this warp's 32 k-cols: transpose P via shuffles, MMA vs Vs
        int srcA = lr * 4 + (lc >> 1);
        int srcB = srcA + 2;
        bool odd = lc & 1;
#pragma unroll
        for (int kb = 0; kb < 4; kb++) {
            float s0 = __shfl_sync(0xffffffffu, s[kb][0], srcA);
            float s1 = __shfl_sync(0xffffffffu, s[kb][1], srcA);
            float s2 = __shfl_sync(0xffffffffu, s[kb][2], srcA);
            float s3 = __shfl_sync(0xffffffffu, s[kb][3], srcA);
            float t0 = __shfl_sync(0xffffffffu, s[kb][0], srcB);
            float t1 = __shfl_sync(0xffffffffu, s[kb][1], srcB);
            float t2 = __shfl_sync(0xffffffffu, s[kb][2], srcB);
            float t3 = __shfl_sync(0xffffffffu, s[kb][3], srcB);
            unsigned a0 = fu(odd ? s1 : s0);
            unsigned a1 = fu(odd ? s3 : s2);
            unsigned a2 = fu(odd ? t1 : t0);
            unsigned a3 = fu(odd ? t3 : t2);
            int kbase = wn * 32 + kb * 8;
#pragma unroll
            for (int od = 0; od < 8; od++) {
                unsigned b0 = fu(Vs[(kbase + lc) * VST + od * 8 + lr]);
                unsigned b1 = fu(Vs[(kbase + lc + 4) * VST + od * 8 + lr]);
                mma_tf32(o[od], a0, a1, a2, a3, b0, b1);
            }
        }
    }

    // Epilogue: sum the two wn-partials via smem (reuse Ks as staging)
    __syncthreads();
    float* Stage = Ks;   // [64][68]
    if (wn == 0) {
#pragma unroll
        for (int od = 0; od < 8; od++) {
            *(float2*)&Stage[row0 * KST + od * 8 + lc * 2] = make_float2(o[od][0], o[od][1]);
            *(float2*)&Stage[row1 * KST + od * 8 + lc * 2] = make_float2(o[od][2], o[od][3]);
        }
    }
    __syncthreads();
    if (wn == 1) {
        float inv0 = 1.f / l0;
        float inv1 = 1.f / l1;
        int r0 = q0 + row0, r1 = q0 + row1;
#pragma unroll
        for (int od = 0; od < 8; od++) {
            int col = h * HDIM + od * 8 + lc * 2;
            float2 p0 = *(float2*)&Stage[row0 * KST + od * 8 + lc * 2];
            float2 p1 = *(float2*)&Stage[row1 * KST + od * 8 + lc * 2];
            if (r0 < SEQ)
                *(float2*)&g_ctx[((size_t)(b * SEQ + r0)) * DIM + col] =
                    make_float2((o[od][0] + p0.x) * inv0, (o[od][1] + p0.y) * inv0);
            if (r1 < SEQ)
                *(float2*)&g_ctx[((size_t)(b * SEQ + r1)) * DIM + col] =
                    make_float2((o[od][2] + p1.x) * inv1, (o[od][3] + p1.y) * inv1);
        }
    }
}

// ---------------------------------------------------------------------------
extern "C" void kernel_launch(void* const* d_in, const int* in_sizes, int n_in,
                              void* d_out, int out_size)
{
    const float* x  = (const float*)d_in[0];
    const float* Wq = (const float*)d_in[1];
    const float* bq = (const float*)d_in[2];
    const float* Wk = (const float*)d_in[3];
    const float* bk = (const float*)d_in[4];
    const float* Wv = (const float*)d_in[5];
    const float* bv = (const float*)d_in[6];
    const float* Wo = (const float*)d_in[7];
    const float* bo = (const float*)d_in[8];
    float* out = (float*)d_out;

    dim3 gemmGrid((MROWS + 127) / 128, DIM / 128);  // 86 x 8

    gemm_tf32<<<gemmGrid, 256>>>(x, Wq, bq, nullptr, 0, 0);
    gemm_tf32<<<gemmGrid, 256>>>(x, Wk, bk, nullptr, 0, 1);
    gemm_tf32<<<gemmGrid, 256>>>(x, Wv, bv, nullptr, 0, 2);

    int smem = (64 * QST + 64 * KST + 64 * VST + 256) * sizeof(float);  // 54272
    cudaFuncSetAttribute(attn_tf32, cudaFuncAttributeMaxDynamicSharedMemorySize, smem);
    dim3 attnGrid((SEQ + 63) / 64, BATCH * HEADS);  // 22 x 128
    attn_tf32<<<attnGrid, 256, smem>>>();

    gemm_tf32<<<gemmGrid, 256>>>(nullptr, Wo, bo, out, 1, 3);
}

// round 6
// speedup vs baseline: 1.3318x; 1.0115x over previous
#include <cuda_runtime.h>
#include <math.h>
#include <stdint.h>

#define BATCH 8
#define SEQ 1370
#define DIM 1024
#define HEADS 16
#define HDIM 64
#define MROWS (BATCH * SEQ)   // 10960

// Scratch (allocation-free: device globals)
__device__ float g_q[BATCH * HEADS * SEQ * HDIM];   // [B,H,S,Dh]
__device__ float g_k[BATCH * HEADS * SEQ * HDIM];
__device__ float g_v[BATCH * HEADS * SEQ * HDIM];
__device__ float g_ctx[BATCH * SEQ * DIM];          // [B,S,D]

__device__ __forceinline__ float to_tf32(float x) {
    float r; asm("cvt.rna.tf32.f32 %0, %1;" : "=f"(r) : "f"(x)); return r;
}
__device__ __forceinline__ unsigned fu(float x) { return __float_as_uint(x); }

__device__ __forceinline__ void mma_tf32(float c[4],
    unsigned a0, unsigned a1, unsigned a2, unsigned a3,
    unsigned b0, unsigned b1)
{
    asm volatile(
        "mma.sync.aligned.m16n8k8.row.col.f32.tf32.tf32.f32 "
        "{%0,%1,%2,%3}, {%4,%5,%6,%7}, {%8,%9}, {%0,%1,%2,%3};"
        : "+f"(c[0]), "+f"(c[1]), "+f"(c[2]), "+f"(c[3])
        : "r"(a0), "r"(a1), "r"(a2), "r"(a3), "r"(b0), "r"(b1));
}

// ---------------------------------------------------------------------------
// TF32 GEMM: C[M,1024] = A[M,1024] @ W[1024,1024] + bias
// 128x128 tile, BK=32, 8 warps (2x4), warp tile 64x32, m16n8k8 tf32 MMA.
// mode 0: fused QKV (blockIdx.z selects W/b/dst, A = x)
// mode 1: output projection (W0/B0 = Wo/bo, A = g_ctx, C = Cext)
// ---------------------------------------------------------------------------
#define GAST 36    // As row stride (36%32==4: conflict-free scalar frags+stores)
#define GBST 136

__device__ __forceinline__ void store_pair(int csel, float* __restrict__ Cext,
                                           int m, int n, float v0, float v1)
{
    if (m >= MROWS) return;
    if (csel <= 2) {
        float* dst = (csel == 0) ? g_q : (csel == 1) ? g_k : g_v;
        int b = m / SEQ;
        int s = m - b * SEQ;
        int h = n >> 6;
        int d = n & 63;
        *(float2*)&dst[(((size_t)(b * HEADS + h)) * SEQ + s) * HDIM + d] =
            make_float2(v0, v1);
    } else {
        *(float2*)&Cext[(size_t)m * DIM + n] = make_float2(v0, v1);
    }
}

__global__ __launch_bounds__(256, 2) void gemm_tf32(
    const float* __restrict__ Aext,
    const float* __restrict__ W0, const float* __restrict__ W1,
    const float* __restrict__ W2,
    const float* __restrict__ B0, const float* __restrict__ B1,
    const float* __restrict__ B2,
    float* __restrict__ Cext, int mode)
{
    __shared__ float As[128 * GAST];
    __shared__ float Bs[32 * GBST];

    int z = blockIdx.z;
    const float* A    = (mode == 1) ? g_ctx : Aext;
    const float* W    = (mode == 1) ? W0 : (z == 0 ? W0 : (z == 1 ? W1 : W2));
    const float* bias = (mode == 1) ? B0 : (z == 0 ? B0 : (z == 1 ? B1 : B2));
    int csel          = (mode == 1) ? 3 : z;

    int tid = threadIdx.x;
    int wid = tid >> 5, lane = tid & 31;
    int wm = wid & 1, wn = wid >> 1;
    int lr = lane >> 2, lc = lane & 3;
    int m0 = blockIdx.x * 128, n0 = blockIdx.y * 128;

    float c[4][4][4];
#pragma unroll
    for (int mt = 0; mt < 4; mt++)
#pragma unroll
        for (int nt = 0; nt < 4; nt++)
#pragma unroll
            for (int i = 0; i < 4; i++) c[mt][nt][i] = 0.f;

    // A loader: 4 float4/thread per BK=32 tile. idx=tid+256i: row=idx>>3, k4=(idx&7)*4
    int arow[4], ak4[4]; bool aval[4];
#pragma unroll
    for (int i = 0; i < 4; i++) {
        int idx = tid + i * 256;
        arow[i] = idx >> 3;
        ak4[i] = (idx & 7) * 4;
        aval[i] = (m0 + arow[i]) < MROWS;
    }
    // B loader: 4 float4/thread. row = tid>>5 + 8i, col4 = (tid&31)*4
    int brow0 = tid >> 5, bn4 = (tid & 31) * 4;

    const float4 z4 = make_float4(0.f, 0.f, 0.f, 0.f);
    float4 ra[4], rb[4];
#pragma unroll
    for (int i = 0; i < 4; i++)
        ra[i] = aval[i] ? *(const float4*)(A + (size_t)(m0 + arow[i]) * DIM + ak4[i]) : z4;
#pragma unroll
    for (int i = 0; i < 4; i++)
        rb[i] = *(const float4*)(W + (size_t)(brow0 + 8 * i) * DIM + n0 + bn4);

    for (int t = 0; t < 32; t++) {
        __syncthreads();
#pragma unroll
        for (int i = 0; i < 4; i++)
            *(float4*)&As[arow[i] * GAST + ak4[i]] = make_float4(
                to_tf32(ra[i].x), to_tf32(ra[i].y), to_tf32(ra[i].z), to_tf32(ra[i].w));
#pragma unroll
        for (int i = 0; i < 4; i++)
            *(float4*)&Bs[(brow0 + 8 * i) * GBST + bn4] = make_float4(
                to_tf32(rb[i].x), to_tf32(rb[i].y), to_tf32(rb[i].z), to_tf32(rb[i].w));
        __syncthreads();

        if (t < 31) {
            int k0 = (t + 1) * 32;
#pragma unroll
            for (int i = 0; i < 4; i++)
                ra[i] = aval[i] ? *(const float4*)(A + (size_t)(m0 + arow[i]) * DIM + k0 + ak4[i]) : z4;
#pragma unroll
            for (int i = 0; i < 4; i++)
                rb[i] = *(const float4*)(W + (size_t)(k0 + brow0 + 8 * i) * DIM + n0 + bn4);
        }

#pragma unroll
        for (int ks = 0; ks < 4; ks++) {
            int kk = ks * 8;
            unsigned bf[4][2];
#pragma unroll
            for (int nt = 0; nt < 4; nt++) {
                int col = wn * 32 + nt * 8 + lr;
                bf[nt][0] = fu(Bs[(kk + lc) * GBST + col]);
                bf[nt][1] = fu(Bs[(kk + lc + 4) * GBST + col]);
            }
#pragma unroll
            for (int mt = 0; mt < 4; mt++) {
                int ar = wm * 64 + mt * 16 + lr;
                unsigned a0 = fu(As[ar * GAST + kk + lc]);
                unsigned a1 = fu(As[(ar + 8) * GAST + kk + lc]);
                unsigned a2 = fu(As[ar * GAST + kk + lc + 4]);
                unsigned a3 = fu(As[(ar + 8) * GAST + kk + lc + 4]);
#pragma unroll
                for (int nt = 0; nt < 4; nt++)
                    mma_tf32(c[mt][nt], a0, a1, a2, a3, bf[nt][0], bf[nt][1]);
            }
        }
    }

#pragma unroll
    for (int mt = 0; mt < 4; mt++) {
        int r0 = m0 + wm * 64 + mt * 16 + lr;
        int r1 = r0 + 8;
#pragma unroll
        for (int nt = 0; nt < 4; nt++) {
            int n = n0 + wn * 32 + nt * 8 + lc * 2;
            float b0v = bias[n], b1v = bias[n + 1];
            store_pair(csel, Cext, r0, n, c[mt][nt][0] + b0v, c[mt][nt][1] + b1v);
            store_pair(csel, Cext, r1, n, c[mt][nt][2] + b0v, c[mt][nt][3] + b1v);
        }
    }
}

// ---------------------------------------------------------------------------
// TF32 split-flash attention: 64 q-rows/CTA, 8 warps (wm 0..3 x wn 0..1).
// Each wn-half runs an INDEPENDENT online softmax over its 32 k-cols
// (own m, l, partial O). No per-tile cross-warp exchange: 2 barriers/tile.
// Halves merged once at the epilogue: O = sum(O_w e^{m_w-M}) / sum(l_w e^{m_w-M}).
// ---------------------------------------------------------------------------
#define QST 68
#define KST 68
#define VST 72

__global__ __launch_bounds__(256) void attn_tf32()
{
    extern __shared__ float sm[];
    float* Qs   = sm;                  // [64][68] pre-scaled tf32
    float* Ks   = Qs + 64 * QST;       // [64][68] (reused as O-stage at end)
    float* Vs   = Ks + 64 * KST;       // [64][72]
    float* m_sh = Vs + 64 * VST;       // [2][64]
    float* l_sh = m_sh + 128;          // [2][64]

    int tid = threadIdx.x;
    int wid = tid >> 5, lane = tid & 31;
    int wm = wid & 3;      // row group (16 rows)
    int wn = wid >> 2;     // k-col group (32 cols)
    int lr = lane >> 2, lc = lane & 3;

    int bh = blockIdx.y;
    int b = bh >> 4;
    int h = bh & 15;
    int q0 = blockIdx.x * 64;

    const float* Qg = g_q + ((size_t)(b * HEADS + h)) * SEQ * HDIM;
    const float* Kg = g_k + ((size_t)(b * HEADS + h)) * SEQ * HDIM;
    const float* Vg = g_v + ((size_t)(b * HEADS + h)) * SEQ * HDIM;

    const float4 z4 = make_float4(0.f, 0.f, 0.f, 0.f);

    // Load Q tile (scaled by 0.125, tf32)
    for (int e = tid; e < 1024; e += 256) {
        int r = e >> 4;
        int d4 = (e & 15) * 4;
        float4 v = (q0 + r < SEQ) ? *(const float4*)(Qg + (size_t)(q0 + r) * HDIM + d4) : z4;
        *(float4*)&Qs[r * QST + d4] = make_float4(
            to_tf32(v.x * 0.125f), to_tf32(v.y * 0.125f),
            to_tf32(v.z * 0.125f), to_tf32(v.w * 0.125f));
    }

    float o[8][4];   // partial O over this warp's 32 k-cols
#pragma unroll
    for (int od = 0; od < 8; od++)
#pragma unroll
        for (int i = 0; i < 4; i++) o[od][i] = 0.f;
    float m0v = -INFINITY, m1v = -INFINITY, l0 = 0.f, l1 = 0.f;

    int row0 = wm * 16 + lr;
    int row1 = row0 + 8;

    for (int k0 = 0; k0 < SEQ; k0 += 64) {
        __syncthreads();  // prev tile done reading Ks/Vs
        for (int e = tid; e < 1024; e += 256) {
            int r = e >> 4;
            int d4 = (e & 15) * 4;
            float4 kv = z4, vv = z4;
            if (k0 + r < SEQ) {
                kv = *(const float4*)(Kg + (size_t)(k0 + r) * HDIM + d4);
                vv = *(const float4*)(Vg + (size_t)(k0 + r) * HDIM + d4);
            }
            *(float4*)&Ks[r * KST + d4] = make_float4(
                to_tf32(kv.x), to_tf32(kv.y), to_tf32(kv.z), to_tf32(kv.w));
            *(float4*)&Vs[r * VST + d4] = make_float4(
                to_tf32(vv.x), to_tf32(vv.y), to_tf32(vv.z), to_tf32(vv.w));
        }
        __syncthreads();

        // S(16x32) = Q @ K^T over this warp's k-cols
        float s[4][4];
#pragma unroll
        for (int nt = 0; nt < 4; nt++)
#pragma unroll
            for (int i = 0; i < 4; i++) s[nt][i] = 0.f;

#pragma unroll
        for (int ks = 0; ks < 8; ks++) {
            int kk = ks * 8;
            int qr = wm * 16 + lr;
            unsigned a0 = fu(Qs[qr * QST + kk + lc]);
            unsigned a1 = fu(Qs[(qr + 8) * QST + kk + lc]);
            unsigned a2 = fu(Qs[qr * QST + kk + lc + 4]);
            unsigned a3 = fu(Qs[(qr + 8) * QST + kk + lc + 4]);
#pragma unroll
            for (int nt = 0; nt < 4; nt++) {
                int krow = wn * 32 + nt * 8 + lr;
                unsigned b0 = fu(Ks[krow * KST + kk + lc]);
                unsigned b1 = fu(Ks[krow * KST + kk + lc + 4]);
                mma_tf32(s[nt], a0, a1, a2, a3, b0, b1);
            }
        }

        // Mask + warp-local row max (quad shuffles) — independent per wn-half
        float rmax0 = -INFINITY, rmax1 = -INFINITY;
#pragma unroll
        for (int nt = 0; nt < 4; nt++) {
#pragma unroll
            for (int e = 0; e < 2; e++) {
                int col = k0 + wn * 32 + nt * 8 + 2 * lc + e;
                if (col >= SEQ) { s[nt][e] = -INFINITY; s[nt][2 + e] = -INFINITY; }
                rmax0 = fmaxf(rmax0, s[nt][e]);
                rmax1 = fmaxf(rmax1, s[nt][2 + e]);
            }
        }
        rmax0 = fmaxf(rmax0, __shfl_xor_sync(0xffffffffu, rmax0, 1));
        rmax0 = fmaxf(rmax0, __shfl_xor_sync(0xffffffffu, rmax0, 2));
        rmax1 = fmaxf(rmax1, __shfl_xor_sync(0xffffffffu, rmax1, 1));
        rmax1 = fmaxf(rmax1, __shfl_xor_sync(0xffffffffu, rmax1, 2));

        float mn0 = fmaxf(m0v, rmax0);
        float mn1 = fmaxf(m1v, rmax1);
        float alpha0 = __expf(m0v - mn0);
        float alpha1 = __expf(m1v - mn1);
        m0v = mn0; m1v = mn1;

        float sum0 = 0.f, sum1 = 0.f;
#pragma unroll
        for (int nt = 0; nt < 4; nt++) {
#pragma unroll
            for (int e = 0; e < 2; e++) {
                float p0 = __expf(s[nt][e] - mn0);
                float p1 = __expf(s[nt][2 + e] - mn1);
                sum0 += p0; sum1 += p1;
                s[nt][e] = to_tf32(p0);
                s[nt][2 + e] = to_tf32(p1);
            }
        }
        sum0 += __shfl_xor_sync(0xffffffffu, sum0, 1);
        sum0 += __shfl_xor_sync(0xffffffffu, sum0, 2);
        sum1 += __shfl_xor_sync(0xffffffffu, sum1, 1);
        sum1 += __shfl_xor_sync(0xffffffffu, sum1, 2);
        l0 = l0 * alpha0 + sum0;
        l1 = l1 * alpha1 + sum1;

#pragma unroll
        for (int od = 0; od < 8; od++) {
            o[od][0] *= alpha0; o[od][1] *= alpha0;
            o[od][2] *= alpha1; o[od][3] *= alpha1;
        }

        // PV over this warp's 32 k-cols: transpose P via shuffles, MMA vs Vs
        int srcA = lr * 4 + (lc >> 1);
        int srcB = srcA + 2;
        bool odd = lc & 1;
#pragma unroll
        for (int kb = 0; kb < 4; kb++) {
            float s0 = __shfl_sync(0xffffffffu, s[kb][0], srcA);
            float s1 = __shfl_sync(0xffffffffu, s[kb][1], srcA);
            float s2 = __shfl_sync(0xffffffffu, s[kb][2], srcA);
            float s3 = __shfl_sync(0xffffffffu, s[kb][3], srcA);
            float t0 = __shfl_sync(0xffffffffu, s[kb][0], srcB);
            float t1 = __shfl_sync(0xffffffffu, s[kb][1], srcB);
            float t2 = __shfl_sync(0xffffffffu, s[kb][2], srcB);
            float t3 = __shfl_sync(0xffffffffu, s[kb][3], srcB);
            unsigned a0 = fu(odd ? s1 : s0);
            unsigned a1 = fu(odd ? s3 : s2);
            unsigned a2 = fu(odd ? t1 : t0);
            unsigned a3 = fu(odd ? t3 : t2);
            int kbase = wn * 32 + kb * 8;
#pragma unroll
            for (int od = 0; od < 8; od++) {
                unsigned b0 = fu(Vs[(kbase + lc) * VST + od * 8 + lr]);
                unsigned b1 = fu(Vs[(kbase + lc + 4) * VST + od * 8 + lr]);
                mma_tf32(o[od], a0, a1, a2, a3, b0, b1);
            }
        }
    }

    // ---- Epilogue: merge the two wn halves (split-softmax combine) ----
    __syncthreads();
    if (lc == 0) {
        m_sh[wn * 64 + row0] = m0v;
        m_sh[wn * 64 + row1] = m1v;
        l_sh[wn * 64 + row0] = l0;
        l_sh[wn * 64 + row1] = l1;
    }
    __syncthreads();
    // global stats per row
    float Ma0 = m_sh[row0], Mb0 = m_sh[64 + row0];
    float Ma1 = m_sh[row1], Mb1 = m_sh[64 + row1];
    float M0 = fmaxf(Ma0, Mb0), M1 = fmaxf(Ma1, Mb1);
    float L0 = l_sh[row0] * __expf(Ma0 - M0) + l_sh[64 + row0] * __expf(Mb0 - M0);
    float L1 = l_sh[row1] * __expf(Ma1 - M1) + l_sh[64 + row1] * __expf(Mb1 - M1);
    float f0 = __expf(m0v - M0);   // this warp's rescale factor
    float f1 = __expf(m1v - M1);

    float* Stage = Ks;   // reuse [64][68]
    if (wn == 0) {
#pragma unroll
        for (int od = 0; od < 8; od++) {
            *(float2*)&Stage[row0 * KST + od * 8 + lc * 2] =
                make_float2(o[od][0] * f0, o[od][1] * f0);
            *(float2*)&Stage[row1 * KST + od * 8 + lc * 2] =
                make_float2(o[od][2] * f1, o[od][3] * f1);
        }
    }
    __syncthreads();
    if (wn == 1) {
        float inv0 = 1.f / L0;
        float inv1 = 1.f / L1;
        int r0 = q0 + row0, r1 = q0 + row1;
#pragma unroll
        for (int od = 0; od < 8; od++) {
            int col = h * HDIM + od * 8 + lc * 2;
            float2 p0 = *(float2*)&Stage[row0 * KST + od * 8 + lc * 2];
            float2 p1 = *(float2*)&Stage[row1 * KST + od * 8 + lc * 2];
            if (r0 < SEQ)
                *(float2*)&g_ctx[((size_t)(b * SEQ + r0)) * DIM + col] =
                    make_float2((o[od][0] * f0 + p0.x) * inv0,
                                (o[od][1] * f0 + p0.y) * inv0);
            if (r1 < SEQ)
                *(float2*)&g_ctx[((size_t)(b * SEQ + r1)) * DIM + col] =
                    make_float2((o[od][2] * f1 + p1.x) * inv1,
                                (o[od][3] * f1 + p1.y) * inv1);
        }
    }
}

// ---------------------------------------------------------------------------
extern "C" void kernel_launch(void* const* d_in, const int* in_sizes, int n_in,
                              void* d_out, int out_size)
{
    const float* x  = (const float*)d_in[0];
    const float* Wq = (const float*)d_in[1];
    const float* bq = (const float*)d_in[2];
    const float* Wk = (const float*)d_in[3];
    const float* bk = (const float*)d_in[4];
    const float* Wv = (const float*)d_in[5];
    const float* bv = (const float*)d_in[6];
    const float* Wo = (const float*)d_in[7];
    const float* bo = (const float*)d_in[8];
    float* out = (float*)d_out;

    // Fused Q/K/V projections (z selects weight/dst)
    dim3 qkvGrid((MROWS + 127) / 128, DIM / 128, 3);  // 86 x 8 x 3
    gemm_tf32<<<qkvGrid, 256>>>(x, Wq, Wk, Wv, bq, bk, bv, nullptr, 0);

    // Attention
    int smem = (64 * QST + 64 * KST + 64 * VST + 256) * sizeof(float);  // 54272
    cudaFuncSetAttribute(attn_tf32, cudaFuncAttributeMaxDynamicSharedMemorySize, smem);
    dim3 attnGrid((SEQ + 63) / 64, BATCH * HEADS);  // 22 x 128
    attn_tf32<<<attnGrid, 256, smem>>>();

    // Output projection
    dim3 oGrid((MROWS + 127) / 128, DIM / 128, 1);
    gemm_tf32<<<oGrid, 256>>>(nullptr, Wo, nullptr, nullptr, bo, nullptr, nullptr, out, 1);
}

// round 7
// speedup vs baseline: 1.7154x; 1.2880x over previous
#include <cuda_runtime.h>
#include <math.h>
#include <stdint.h>

#define BATCH 8
#define SEQ 1370
#define DIM 1024
#define HEADS 16
#define HDIM 64
#define MROWS (BATCH * SEQ)   // 10960

// Scratch (allocation-free: device globals)
__device__ __align__(256) float g_q[BATCH * HEADS * SEQ * HDIM];   // [B,H,S,Dh] tf32, Q pre-scaled
__device__ __align__(256) float g_k[BATCH * HEADS * SEQ * HDIM];
__device__ __align__(256) float g_v[BATCH * HEADS * SEQ * HDIM];
__device__ __align__(256) float g_ctx[BATCH * SEQ * DIM];          // [B,S,D] tf32
__device__ __align__(256) float g_xr[MROWS * DIM];                 // x rounded to tf32
__device__ __align__(256) float g_wr[4 * DIM * DIM];               // Wq,Wk,Wv,Wo rounded

__device__ __forceinline__ float to_tf32(float x) {
    float r; asm("cvt.rna.tf32.f32 %0, %1;" : "=f"(r) : "f"(x)); return r;
}
__device__ __forceinline__ unsigned fu(float x) { return __float_as_uint(x); }

__device__ __forceinline__ void mma_tf32(float c[4],
    unsigned a0, unsigned a1, unsigned a2, unsigned a3,
    unsigned b0, unsigned b1)
{
    asm volatile(
        "mma.sync.aligned.m16n8k8.row.col.f32.tf32.tf32.f32 "
        "{%0,%1,%2,%3}, {%4,%5,%6,%7}, {%8,%9}, {%0,%1,%2,%3};"
        : "+f"(c[0]), "+f"(c[1]), "+f"(c[2]), "+f"(c[3])
        : "r"(a0), "r"(a1), "r"(a2), "r"(a3), "r"(b0), "r"(b1));
}

// ---- cp.async helpers ----
__device__ __forceinline__ void cp16(void* smem_dst, const void* gsrc, bool pred) {
    unsigned d = (unsigned)__cvta_generic_to_shared(smem_dst);
    int sz = pred ? 16 : 0;
    asm volatile("cp.async.cg.shared.global [%0], [%1], 16, %2;\n"
                 :: "r"(d), "l"(gsrc), "r"(sz));
}
#define CP_COMMIT() asm volatile("cp.async.commit_group;\n")
#define CP_WAIT0()  asm volatile("cp.async.wait_group 0;\n" ::: "memory")

// ---------------------------------------------------------------------------
// Pre-rounding passes (inputs -> tf32 bit patterns)
// ---------------------------------------------------------------------------
__global__ __launch_bounds__(256) void round_x(const float* __restrict__ x)
{
    int i = blockIdx.x * blockDim.x + threadIdx.x;   // < MROWS*DIM/4
    if (i >= MROWS * DIM / 4) return;
    float4 v = ((const float4*)x)[i];
    ((float4*)g_xr)[i] = make_float4(to_tf32(v.x), to_tf32(v.y), to_tf32(v.z), to_tf32(v.w));
}

__global__ __launch_bounds__(256) void round_w(
    const float* __restrict__ wq, const float* __restrict__ wk,
    const float* __restrict__ wv, const float* __restrict__ wo)
{
    int i = blockIdx.x * blockDim.x + threadIdx.x;   // < 4 * DIM*DIM/4
    int w = i >> 18;            // DIM*DIM/4 = 262144 = 2^18
    int j = i & 262143;
    const float* s = (w == 0) ? wq : (w == 1) ? wk : (w == 2) ? wv : wo;
    float4 v = ((const float4*)s)[j];
    ((float4*)g_wr)[i] = make_float4(to_tf32(v.x), to_tf32(v.y), to_tf32(v.z), to_tf32(v.w));
}

// ---------------------------------------------------------------------------
// TF32 GEMM with cp.async double-buffer. C = A @ W + bias.
// 128x128 tile, BK=32, 8 warps (2x4), warp tile 64x32. 1 barrier/iter.
// mode 0: fused QKV (z selects W/bias/dst; A = g_xr)
// mode 1: out proj (A = g_ctx, W = g_wr[3], bias = B0, C = Cext)
// ---------------------------------------------------------------------------
#define GAST 36
#define GBST 136
#define ASTG (128 * GAST)
#define BSTG (32 * GBST)

__device__ __forceinline__ void store_pair(int csel, float* __restrict__ Cext,
                                           int m, int n, float v0, float v1)
{
    if (m >= MROWS) return;
    if (csel <= 2) {
        float* dst = (csel == 0) ? g_q : (csel == 1) ? g_k : g_v;
        if (csel == 0) { v0 = to_tf32(v0 * 0.125f); v1 = to_tf32(v1 * 0.125f); }
        else           { v0 = to_tf32(v0);          v1 = to_tf32(v1); }
        int b = m / SEQ;
        int s = m - b * SEQ;
        int h = n >> 6;
        int d = n & 63;
        *(float2*)&dst[(((size_t)(b * HEADS + h)) * SEQ + s) * HDIM + d] =
            make_float2(v0, v1);
    } else {
        *(float2*)&Cext[(size_t)m * DIM + n] = make_float2(v0, v1);
    }
}

__global__ __launch_bounds__(256, 2) void gemm_tf32(
    const float* __restrict__ B0, const float* __restrict__ B1,
    const float* __restrict__ B2, float* __restrict__ Cext, int mode)
{
    extern __shared__ float smg[];
    float* As = smg;               // [2][ASTG]
    float* Bs = smg + 2 * ASTG;    // [2][BSTG]

    int z = (mode == 1) ? 3 : blockIdx.z;
    const float* A    = (mode == 1) ? g_ctx : g_xr;
    const float* W    = g_wr + (size_t)z * DIM * DIM;
    const float* bias = (mode == 1) ? B0 : (z == 0 ? B0 : (z == 1 ? B1 : B2));
    int csel          = (mode == 1) ? 3 : z;

    int tid = threadIdx.x;
    int wid = tid >> 5, lane = tid & 31;
    int wm = wid & 1, wn = wid >> 1;
    int lr = lane >> 2, lc = lane & 3;
    int m0 = blockIdx.x * 128, n0 = blockIdx.y * 128;

    float c[4][4][4];
#pragma unroll
    for (int mt = 0; mt < 4; mt++)
#pragma unroll
        for (int nt = 0; nt < 4; nt++)
#pragma unroll
            for (int i = 0; i < 4; i++) c[mt][nt][i] = 0.f;

    // A loader: 4 cp16/thread. idx=tid+256i: row=idx>>3, k4=(idx&7)*4
    int arow[4], ak4[4]; bool aval[4];
#pragma unroll
    for (int i = 0; i < 4; i++) {
        int idx = tid + i * 256;
        arow[i] = idx >> 3;
        ak4[i] = (idx & 7) * 4;
        aval[i] = (m0 + arow[i]) < MROWS;
    }
    // B loader: 4 cp16/thread. row = tid>>5 + 8i, col4 = (tid&31)*4
    int brow0 = tid >> 5, bn4 = (tid & 31) * 4;

#define G_ISSUE(T, S)                                                           \
    do {                                                                        \
        int _k0 = (T) * 32;                                                     \
        float* _Asd = As + (S) * ASTG;                                          \
        float* _Bsd = Bs + (S) * BSTG;                                          \
        _Pragma("unroll")                                                       \
        for (int _i = 0; _i < 4; _i++)                                          \
            cp16(_Asd + arow[_i] * GAST + ak4[_i],                              \
                 A + (size_t)(m0 + arow[_i]) * DIM + _k0 + ak4[_i], aval[_i]);  \
        _Pragma("unroll")                                                       \
        for (int _i = 0; _i < 4; _i++)                                          \
            cp16(_Bsd + (brow0 + 8 * _i) * GBST + bn4,                          \
                 W + (size_t)(_k0 + brow0 + 8 * _i) * DIM + n0 + bn4, true);    \
        CP_COMMIT();                                                            \
    } while (0)

    G_ISSUE(0, 0);

    for (int t = 0; t < 32; t++) {
        CP_WAIT0();
        __syncthreads();
        if (t + 1 < 32) G_ISSUE(t + 1, (t + 1) & 1);

        const float* Asb = As + (t & 1) * ASTG;
        const float* Bsb = Bs + (t & 1) * BSTG;

#pragma unroll
        for (int ks = 0; ks < 4; ks++) {
            int kk = ks * 8;
            unsigned bf[4][2];
#pragma unroll
            for (int nt = 0; nt < 4; nt++) {
                int col = wn * 32 + nt * 8 + lr;
                bf[nt][0] = fu(Bsb[(kk + lc) * GBST + col]);
                bf[nt][1] = fu(Bsb[(kk + lc + 4) * GBST + col]);
            }
#pragma unroll
            for (int mt = 0; mt < 4; mt++) {
                int ar = wm * 64 + mt * 16 + lr;
                unsigned a0 = fu(Asb[ar * GAST + kk + lc]);
                unsigned a1 = fu(Asb[(ar + 8) * GAST + kk + lc]);
                unsigned a2 = fu(Asb[ar * GAST + kk + lc + 4]);
                unsigned a3 = fu(Asb[(ar + 8) * GAST + kk + lc + 4]);
#pragma unroll
                for (int nt = 0; nt < 4; nt++)
                    mma_tf32(c[mt][nt], a0, a1, a2, a3, bf[nt][0], bf[nt][1]);
            }
        }
    }

#pragma unroll
    for (int mt = 0; mt < 4; mt++) {
        int r0 = m0 + wm * 64 + mt * 16 + lr;
        int r1 = r0 + 8;
#pragma unroll
        for (int nt = 0; nt < 4; nt++) {
            int n = n0 + wn * 32 + nt * 8 + lc * 2;
            float b0v = bias[n], b1v = bias[n + 1];
            store_pair(csel, Cext, r0, n, c[mt][nt][0] + b0v, c[mt][nt][1] + b1v);
            store_pair(csel, Cext, r1, n, c[mt][nt][2] + b0v, c[mt][nt][3] + b1v);
        }
    }
}

// ---------------------------------------------------------------------------
// TF32 split-flash attention with cp.async double-buffered K/V.
// 64 q-rows/CTA, 8 warps (wm 0..3 x wn 0..1), independent online softmax per
// wn-half, epilogue merge. 1 barrier per k-tile.
// ---------------------------------------------------------------------------
#define QST 68
#define KST 68
#define VST 72
#define NT  ((SEQ + 63) / 64)   // 22

__global__ __launch_bounds__(256, 2) void attn_tf32()
{
    extern __shared__ float sma[];
    float* Qs   = sma;                       // [64][68]
    float* Ks   = Qs + 64 * QST;             // [2][64][68]
    float* Vs   = Ks + 2 * 64 * KST;         // [2][64][72]
    float* m_sh = Vs + 2 * 64 * VST;         // [2][64]
    float* l_sh = m_sh + 128;                // [2][64]

    int tid = threadIdx.x;
    int wid = tid >> 5, lane = tid & 31;
    int wm = wid & 3;      // row group (16 rows)
    int wn = wid >> 2;     // k-col group (32 cols)
    int lr = lane >> 2, lc = lane & 3;

    int bh = blockIdx.y;
    int b = bh >> 4;
    int h = bh & 15;
    int q0 = blockIdx.x * 64;

    const float* Qg = g_q + ((size_t)(b * HEADS + h)) * SEQ * HDIM;
    const float* Kg = g_k + ((size_t)(b * HEADS + h)) * SEQ * HDIM;
    const float* Vg = g_v + ((size_t)(b * HEADS + h)) * SEQ * HDIM;

    const float4 z4 = make_float4(0.f, 0.f, 0.f, 0.f);

    // Q tile: plain copy (already tf32 + pre-scaled)
    for (int e = tid; e < 1024; e += 256) {
        int r = e >> 4;
        int d4 = (e & 15) * 4;
        float4 v = (q0 + r < SEQ) ? *(const float4*)(Qg + (size_t)(q0 + r) * HDIM + d4) : z4;
        *(float4*)&Qs[r * QST + d4] = v;
    }

#define A_ISSUE(T, S)                                                         \
    do {                                                                      \
        int _k0 = (T) * 64;                                                   \
        float* _Kd = Ks + (S) * 64 * KST;                                     \
        float* _Vd = Vs + (S) * 64 * VST;                                     \
        _Pragma("unroll")                                                     \
        for (int _i = 0; _i < 4; _i++) {                                      \
            int _idx = tid + _i * 256;                                        \
            int _r = _idx >> 4;                                               \
            int _d4 = (_idx & 15) * 4;                                        \
            bool _ok = (_k0 + _r) < SEQ;                                      \
            cp16(_Kd + _r * KST + _d4, Kg + (size_t)(_k0 + _r) * HDIM + _d4, _ok); \
            cp16(_Vd + _r * VST + _d4, Vg + (size_t)(_k0 + _r) * HDIM + _d4, _ok); \
        }                                                                     \
        CP_COMMIT();                                                          \
    } while (0)

    float o[8][4];
#pragma unroll
    for (int od = 0; od < 8; od++)
#pragma unroll
        for (int i = 0; i < 4; i++) o[od][i] = 0.f;
    float m0v = -INFINITY, m1v = -INFINITY, l0 = 0.f, l1 = 0.f;

    int row0 = wm * 16 + lr;
    int row1 = row0 + 8;

    A_ISSUE(0, 0);

    for (int t = 0; t < NT; t++) {
        CP_WAIT0();
        __syncthreads();
        if (t + 1 < NT) A_ISSUE(t + 1, (t + 1) & 1);

        const float* Ksb = Ks + (t & 1) * 64 * KST;
        const float* Vsb = Vs + (t & 1) * 64 * VST;
        int k0 = t * 64;

        // S(16x32) = Q @ K^T over this warp's k-cols
        float s[4][4];
#pragma unroll
        for (int nt = 0; nt < 4; nt++)
#pragma unroll
            for (int i = 0; i < 4; i++) s[nt][i] = 0.f;

#pragma unroll
        for (int ks = 0; ks < 8; ks++) {
            int kk = ks * 8;
            int qr = wm * 16 + lr;
            unsigned a0 = fu(Qs[qr * QST + kk + lc]);
            unsigned a1 = fu(Qs[(qr + 8) * QST + kk + lc]);
            unsigned a2 = fu(Qs[qr * QST + kk + lc + 4]);
            unsigned a3 = fu(Qs[(qr + 8) * QST + kk + lc + 4]);
#pragma unroll
            for (int nt = 0; nt < 4; nt++) {
                int krow = wn * 32 + nt * 8 + lr;
                unsigned b0 = fu(Ksb[krow * KST + kk + lc]);
                unsigned b1 = fu(Ksb[krow * KST + kk + lc + 4]);
                mma_tf32(s[nt], a0, a1, a2, a3, b0, b1);
            }
        }

        // Mask + warp-local row max (quad shuffles), independent per wn-half
        float rmax0 = -INFINITY, rmax1 = -INFINITY;
#pragma unroll
        for (int nt = 0; nt < 4; nt++) {
#pragma unroll
            for (int e = 0; e < 2; e++) {
                int col = k0 + wn * 32 + nt * 8 + 2 * lc + e;
                if (col >= SEQ) { s[nt][e] = -INFINITY; s[nt][2 + e] = -INFINITY; }
                rmax0 = fmaxf(rmax0, s[nt][e]);
                rmax1 = fmaxf(rmax1, s[nt][2 + e]);
            }
        }
        rmax0 = fmaxf(rmax0, __shfl_xor_sync(0xffffffffu, rmax0, 1));
        rmax0 = fmaxf(rmax0, __shfl_xor_sync(0xffffffffu, rmax0, 2));
        rmax1 = fmaxf(rmax1, __shfl_xor_sync(0xffffffffu, rmax1, 1));
        rmax1 = fmaxf(rmax1, __shfl_xor_sync(0xffffffffu, rmax1, 2));

        float mn0 = fmaxf(m0v, rmax0);
        float mn1 = fmaxf(m1v, rmax1);
        float alpha0 = __expf(m0v - mn0);
        float alpha1 = __expf(m1v - mn1);
        m0v = mn0; m1v = mn1;

        float sum0 = 0.f, sum1 = 0.f;
#pragma unroll
        for (int nt = 0; nt < 4; nt++) {
#pragma unroll
            for (int e = 0; e < 2; e++) {
                float p0 = __expf(s[nt][e] - mn0);
                float p1 = __expf(s[nt][2 + e] - mn1);
                sum0 += p0; sum1 += p1;
                s[nt][e] = to_tf32(p0);
                s[nt][2 + e] = to_tf32(p1);
            }
        }
        sum0 += __shfl_xor_sync(0xffffffffu, sum0, 1);
        sum0 += __shfl_xor_sync(0xffffffffu, sum0, 2);
        sum1 += __shfl_xor_sync(0xffffffffu, sum1, 1);
        sum1 += __shfl_xor_sync(0xffffffffu, sum1, 2);
        l0 = l0 * alpha0 + sum0;
        l1 = l1 * alpha1 + sum1;

#pragma unroll
        for (int od = 0; od < 8; od++) {
            o[od][0] *= alpha0; o[od][1] *= alpha0;
            o[od][2] *= alpha1; o[od][3] *= alpha1;
        }

        // PV over this warp's 32 k-cols: transpose P via shuffles, MMA vs V
        int srcA = lr * 4 + (lc >> 1);
        int srcB = srcA + 2;
        bool odd = lc & 1;
#pragma unroll
        for (int kb = 0; kb < 4; kb++) {
            float s0 = __shfl_sync(0xffffffffu, s[kb][0], srcA);
            float s1 = __shfl_sync(0xffffffffu, s[kb][1], srcA);
            float s2 = __shfl_sync(0xffffffffu, s[kb][2], srcA);
            float s3 = __shfl_sync(0xffffffffu, s[kb][3], srcA);
            float t0 = __shfl_sync(0xffffffffu, s[kb][0], srcB);
            float t1 = __shfl_sync(0xffffffffu, s[kb][1], srcB);
            float t2 = __shfl_sync(0xffffffffu, s[kb][2], srcB);
            float t3 = __shfl_sync(0xffffffffu, s[kb][3], srcB);
            unsigned a0 = fu(odd ? s1 : s0);
            unsigned a1 = fu(odd ? s3 : s2);
            unsigned a2 = fu(odd ? t1 : t0);
            unsigned a3 = fu(odd ? t3 : t2);
            int kbase = wn * 32 + kb * 8;
#pragma unroll
            for (int od = 0; od < 8; od++) {
                unsigned b0 = fu(Vsb[(kbase + lc) * VST + od * 8 + lr]);
                unsigned b1 = fu(Vsb[(kbase + lc + 4) * VST + od * 8 + lr]);
                mma_tf32(o[od], a0, a1, a2, a3, b0, b1);
            }
        }
    }

    // ---- Epilogue: merge the two wn halves (split-softmax combine) ----
    __syncthreads();
    if (lc == 0) {
        m_sh[wn * 64 + row0] = m0v;
        m_sh[wn * 64 + row1] = m1v;
        l_sh[wn * 64 + row0] = l0;
        l_sh[wn * 64 + row1] = l1;
    }
    __syncthreads();
    float Ma0 = m_sh[row0], Mb0 = m_sh[64 + row0];
    float Ma1 = m_sh[row1], Mb1 = m_sh[64 + row1];
    float M0 = fmaxf(Ma0, Mb0), M1 = fmaxf(Ma1, Mb1);
    float L0 = l_sh[row0] * __expf(Ma0 - M0) + l_sh[64 + row0] * __expf(Mb0 - M0);
    float L1 = l_sh[row1] * __expf(Ma1 - M1) + l_sh[64 + row1] * __expf(Mb1 - M1);
    float f0 = __expf(m0v - M0);
    float f1 = __expf(m1v - M1);

    float* Stage = Ks;   // reuse K stage-0 buffer [64][68]
    if (wn == 0) {
#pragma unroll
        for (int od = 0; od < 8; od++) {
            *(float2*)&Stage[row0 * KST + od * 8 + lc * 2] =
                make_float2(o[od][0] * f0, o[od][1] * f0);
            *(float2*)&Stage[row1 * KST + od * 8 + lc * 2] =
                make_float2(o[od][2] * f1, o[od][3] * f1);
        }
    }
    __syncthreads();
    if (wn == 1) {
        float inv0 = 1.f / L0;
        float inv1 = 1.f / L1;
        int r0 = q0 + row0, r1 = q0 + row1;
#pragma unroll
        for (int od = 0; od < 8; od++) {
            int col = h * HDIM + od * 8 + lc * 2;
            float2 p0 = *(float2*)&Stage[row0 * KST + od * 8 + lc * 2];
            float2 p1 = *(float2*)&Stage[row1 * KST + od * 8 + lc * 2];
            if (r0 < SEQ)
                *(float2*)&g_ctx[((size_t)(b * SEQ + r0)) * DIM + col] =
                    make_float2(to_tf32((o[od][0] * f0 + p0.x) * inv0),
                                to_tf32((o[od][1] * f0 + p0.y) * inv0));
            if (r1 < SEQ)
                *(float2*)&g_ctx[((size_t)(b * SEQ + r1)) * DIM + col] =
                    make_float2(to_tf32((o[od][2] * f1 + p1.x) * inv1),
                                to_tf32((o[od][3] * f1 + p1.y) * inv1));
        }
    }
}

// ---------------------------------------------------------------------------
extern "C" void kernel_launch(void* const* d_in, const int* in_sizes, int n_in,
                              void* d_out, int out_size)
{
    const float* x  = (const float*)d_in[0];
    const float* Wq = (const float*)d_in[1];
    const float* bq = (const float*)d_in[2];
    const float* Wk = (const float*)d_in[3];
    const float* bk = (const float*)d_in[4];
    const float* Wv = (const float*)d_in[5];
    const float* bv = (const float*)d_in[6];
    const float* Wo = (const float*)d_in[7];
    const float* bo = (const float*)d_in[8];
    float* out = (float*)d_out;

    // Pre-round inputs to tf32 bit patterns
    round_x<<<(MROWS * DIM / 4 + 255) / 256, 256>>>(x);
    round_w<<<(4 * DIM * DIM / 4 + 255) / 256, 256>>>(Wq, Wk, Wv, Wo);

    int gsm = (2 * ASTG + 2 * BSTG) * sizeof(float);   // 71680
    cudaFuncSetAttribute(gemm_tf32, cudaFuncAttributeMaxDynamicSharedMemorySize, gsm);

    // Fused Q/K/V projections
    dim3 qkvGrid((MROWS + 127) / 128, DIM / 128, 3);  // 86 x 8 x 3
    gemm_tf32<<<qkvGrid, 256, gsm>>>(bq, bk, bv, nullptr, 0);

    // Attention
    int asm_ = (64 * QST + 2 * 64 * KST + 2 * 64 * VST + 256) * sizeof(float);  // 90112
    cudaFuncSetAttribute(attn_tf32, cudaFuncAttributeMaxDynamicSharedMemorySize, asm_);
    dim3 attnGrid((SEQ + 63) / 64, BATCH * HEADS);  // 22 x 128
    attn_tf32<<<attnGrid, 256, asm_>>>();

    // Output projection
    dim3 oGrid((MROWS + 127) / 128, DIM / 128, 1);
    gemm_tf32<<<oGrid, 256, gsm>>>(bo, nullptr, nullptr, out, 1);
}

// round 8
// speedup vs baseline: 1.7312x; 1.0092x over previous
#include <cuda_runtime.h>
#include <math.h>
#include <stdint.h>

#define BATCH 8
#define SEQ 1370
#define DIM 1024
#define HEADS 16
#define HDIM 64
#define MROWS (BATCH * SEQ)   // 10960

// Q pre-scale: 1/sqrt(64) * log2(e)  (softmax computed in base-2 domain)
#define QSCALE 0.18033688011112042f

// Scratch (allocation-free: device globals)
__device__ __align__(256) float g_q[BATCH * HEADS * SEQ * HDIM];   // [B,H,S,Dh] tf32, pre-scaled
__device__ __align__(256) float g_k[BATCH * HEADS * SEQ * HDIM];
__device__ __align__(256) float g_v[BATCH * HEADS * SEQ * HDIM];
__device__ __align__(256) float g_ctx[BATCH * SEQ * DIM];          // [B,S,D] tf32
__device__ __align__(256) float g_xr[MROWS * DIM];                 // x rounded to tf32
__device__ __align__(256) float g_wr[4 * DIM * DIM];               // Wq,Wk,Wv,Wo rounded

__device__ __forceinline__ float to_tf32(float x) {
    float r; asm("cvt.rna.tf32.f32 %0, %1;" : "=f"(r) : "f"(x)); return r;
}
__device__ __forceinline__ unsigned fu(float x) { return __float_as_uint(x); }
__device__ __forceinline__ float ex2(float x) {
    float r; asm("ex2.approx.f32 %0, %1;" : "=f"(r) : "f"(x)); return r;
}

__device__ __forceinline__ void mma_tf32(float c[4],
    unsigned a0, unsigned a1, unsigned a2, unsigned a3,
    unsigned b0, unsigned b1)
{
    asm volatile(
        "mma.sync.aligned.m16n8k8.row.col.f32.tf32.tf32.f32 "
        "{%0,%1,%2,%3}, {%4,%5,%6,%7}, {%8,%9}, {%0,%1,%2,%3};"
        : "+f"(c[0]), "+f"(c[1]), "+f"(c[2]), "+f"(c[3])
        : "r"(a0), "r"(a1), "r"(a2), "r"(a3), "r"(b0), "r"(b1));
}

// ---- cp.async helpers ----
__device__ __forceinline__ void cp16(void* smem_dst, const void* gsrc, bool pred) {
    unsigned d = (unsigned)__cvta_generic_to_shared(smem_dst);
    int sz = pred ? 16 : 0;
    asm volatile("cp.async.cg.shared.global [%0], [%1], 16, %2;\n"
                 :: "r"(d), "l"(gsrc), "r"(sz));
}
#define CP_COMMIT() asm volatile("cp.async.commit_group;\n")
#define CP_WAIT0()  asm volatile("cp.async.wait_group 0;\n" ::: "memory")
#define CP_WAIT1()  asm volatile("cp.async.wait_group 1;\n" ::: "memory")

// ---------------------------------------------------------------------------
// Pre-rounding passes
// ---------------------------------------------------------------------------
__global__ __launch_bounds__(256) void round_x(const float* __restrict__ x)
{
    int i = blockIdx.x * blockDim.x + threadIdx.x;
    if (i >= MROWS * DIM / 4) return;
    float4 v = ((const float4*)x)[i];
    ((float4*)g_xr)[i] = make_float4(to_tf32(v.x), to_tf32(v.y), to_tf32(v.z), to_tf32(v.w));
}

__global__ __launch_bounds__(256) void round_w(
    const float* __restrict__ wq, const float* __restrict__ wk,
    const float* __restrict__ wv, const float* __restrict__ wo)
{
    int i = blockIdx.x * blockDim.x + threadIdx.x;
    int w = i >> 18;
    int j = i & 262143;
    const float* s = (w == 0) ? wq : (w == 1) ? wk : (w == 2) ? wv : wo;
    float4 v = ((const float4*)s)[j];
    ((float4*)g_wr)[i] = make_float4(to_tf32(v.x), to_tf32(v.y), to_tf32(v.z), to_tf32(v.w));
}

// ---------------------------------------------------------------------------
// TF32 GEMM, 3-stage cp.async pipeline. C = A @ W + bias.
// 128x128 tile, BK=32, 8 warps (2x4), warp tile 64x32.
// ---------------------------------------------------------------------------
#define GAST 36
#define GBST 136
#define ASTG (128 * GAST)
#define BSTG (32 * GBST)

__device__ __forceinline__ void store_pair(int csel, float* __restrict__ Cext,
                                           int m, int n, float v0, float v1)
{
    if (m >= MROWS) return;
    if (csel <= 2) {
        float* dst = (csel == 0) ? g_q : (csel == 1) ? g_k : g_v;
        if (csel == 0) { v0 = to_tf32(v0 * QSCALE); v1 = to_tf32(v1 * QSCALE); }
        else           { v0 = to_tf32(v0);          v1 = to_tf32(v1); }
        int b = m / SEQ;
        int s = m - b * SEQ;
        int h = n >> 6;
        int d = n & 63;
        *(float2*)&dst[(((size_t)(b * HEADS + h)) * SEQ + s) * HDIM + d] =
            make_float2(v0, v1);
    } else {
        *(float2*)&Cext[(size_t)m * DIM + n] = make_float2(v0, v1);
    }
}

__global__ __launch_bounds__(256, 2) void gemm_tf32(
    const float* __restrict__ B0, const float* __restrict__ B1,
    const float* __restrict__ B2, float* __restrict__ Cext, int mode)
{
    extern __shared__ float smg[];
    float* As = smg;               // [3][ASTG]
    float* Bs = smg + 3 * ASTG;    // [3][BSTG]

    int z = (mode == 1) ? 3 : blockIdx.z;
    const float* A    = (mode == 1) ? g_ctx : g_xr;
    const float* W    = g_wr + (size_t)z * DIM * DIM;
    const float* bias = (mode == 1) ? B0 : (z == 0 ? B0 : (z == 1 ? B1 : B2));
    int csel          = (mode == 1) ? 3 : z;

    int tid = threadIdx.x;
    int wid = tid >> 5, lane = tid & 31;
    int wm = wid & 1, wn = wid >> 1;
    int lr = lane >> 2, lc = lane & 3;
    int m0 = blockIdx.x * 128, n0 = blockIdx.y * 128;

    float c[4][4][4];
#pragma unroll
    for (int mt = 0; mt < 4; mt++)
#pragma unroll
        for (int nt = 0; nt < 4; nt++)
#pragma unroll
            for (int i = 0; i < 4; i++) c[mt][nt][i] = 0.f;

    int arow[4], ak4[4]; bool aval[4];
#pragma unroll
    for (int i = 0; i < 4; i++) {
        int idx = tid + i * 256;
        arow[i] = idx >> 3;
        ak4[i] = (idx & 7) * 4;
        aval[i] = (m0 + arow[i]) < MROWS;
    }
    int brow0 = tid >> 5, bn4 = (tid & 31) * 4;

#define G_ISSUE(T, S)                                                           \
    do {                                                                        \
        int _k0 = (T) * 32;                                                     \
        float* _Asd = As + (S) * ASTG;                                          \
        float* _Bsd = Bs + (S) * BSTG;                                          \
        _Pragma("unroll")                                                       \
        for (int _i = 0; _i < 4; _i++)                                          \
            cp16(_Asd + arow[_i] * GAST + ak4[_i],                              \
                 A + (size_t)(m0 + arow[_i]) * DIM + _k0 + ak4[_i], aval[_i]);  \
        _Pragma("unroll")                                                       \
        for (int _i = 0; _i < 4; _i++)                                          \
            cp16(_Bsd + (brow0 + 8 * _i) * GBST + bn4,                          \
                 W + (size_t)(_k0 + brow0 + 8 * _i) * DIM + n0 + bn4, true);    \
        CP_COMMIT();                                                            \
    } while (0)

    G_ISSUE(0, 0);
    G_ISSUE(1, 1);

    int st = 0;   // t % 3
    for (int t = 0; t < 32; t++) {
        if (t + 2 < 32) CP_WAIT1(); else CP_WAIT0();
        __syncthreads();
        if (t + 2 < 32) {
            int s2 = st + 2; if (s2 >= 3) s2 -= 3;
            G_ISSUE(t + 2, s2);
        }

        const float* Asb = As + st * ASTG;
        const float* Bsb = Bs + st * BSTG;

#pragma unroll
        for (int ks = 0; ks < 4; ks++) {
            int kk = ks * 8;
            unsigned bf[4][2];
#pragma unroll
            for (int nt = 0; nt < 4; nt++) {
                int col = wn * 32 + nt * 8 + lr;
                bf[nt][0] = fu(Bsb[(kk + lc) * GBST + col]);
                bf[nt][1] = fu(Bsb[(kk + lc + 4) * GBST + col]);
            }
#pragma unroll
            for (int mt = 0; mt < 4; mt++) {
                int ar = wm * 64 + mt * 16 + lr;
                unsigned a0 = fu(Asb[ar * GAST + kk + lc]);
                unsigned a1 = fu(Asb[(ar + 8) * GAST + kk + lc]);
                unsigned a2 = fu(Asb[ar * GAST + kk + lc + 4]);
                unsigned a3 = fu(Asb[(ar + 8) * GAST + kk + lc + 4]);
#pragma unroll
                for (int nt = 0; nt < 4; nt++)
                    mma_tf32(c[mt][nt], a0, a1, a2, a3, bf[nt][0], bf[nt][1]);
            }
        }
        if (++st == 3) st = 0;
    }

#pragma unroll
    for (int mt = 0; mt < 4; mt++) {
        int r0 = m0 + wm * 64 + mt * 16 + lr;
        int r1 = r0 + 8;
#pragma unroll
        for (int nt = 0; nt < 4; nt++) {
            int n = n0 + wn * 32 + nt * 8 + lc * 2;
            float b0v = bias[n], b1v = bias[n + 1];
            store_pair(csel, Cext, r0, n, c[mt][nt][0] + b0v, c[mt][nt][1] + b1v);
            store_pair(csel, Cext, r1, n, c[mt][nt][2] + b0v, c[mt][nt][3] + b1v);
        }
    }
}

// ---------------------------------------------------------------------------
// TF32 split-flash attention, cp.async 2-stage K/V, base-2 softmax.
// 64 q-rows/CTA, 8 warps (wm 0..3 x wn 0..1), independent online softmax per
// wn-half (own m,l,partial O in log2 domain), epilogue merge. 1 barrier/tile.
// ---------------------------------------------------------------------------
#define QST 68
#define KST 68
#define VST 72
#define NT  ((SEQ + 63) / 64)   // 22

__global__ __launch_bounds__(256, 2) void attn_tf32()
{
    extern __shared__ float sma[];
    float* Qs   = sma;                       // [64][68]
    float* Ks   = Qs + 64 * QST;             // [2][64][68]
    float* Vs   = Ks + 2 * 64 * KST;         // [2][64][72]
    float* m_sh = Vs + 2 * 64 * VST;         // [2][64]
    float* l_sh = m_sh + 128;                // [2][64]

    int tid = threadIdx.x;
    int wid = tid >> 5, lane = tid & 31;
    int wm = wid & 3;
    int wn = wid >> 2;
    int lr = lane >> 2, lc = lane & 3;

    int bh = blockIdx.y;
    int b = bh >> 4;
    int h = bh & 15;
    int q0 = blockIdx.x * 64;

    const float* Qg = g_q + ((size_t)(b * HEADS + h)) * SEQ * HDIM;
    const float* Kg = g_k + ((size_t)(b * HEADS + h)) * SEQ * HDIM;
    const float* Vg = g_v + ((size_t)(b * HEADS + h)) * SEQ * HDIM;

    const float4 z4 = make_float4(0.f, 0.f, 0.f, 0.f);

    // Q tile: plain copy (already tf32 + pre-scaled by 0.125*log2e)
    for (int e = tid; e < 1024; e += 256) {
        int r = e >> 4;
        int d4 = (e & 15) * 4;
        float4 v = (q0 + r < SEQ) ? *(const float4*)(Qg + (size_t)(q0 + r) * HDIM + d4) : z4;
        *(float4*)&Qs[r * QST + d4] = v;
    }

#define A_ISSUE(T, S)                                                         \
    do {                                                                      \
        int _k0 = (T) * 64;                                                   \
        float* _Kd = Ks + (S) * 64 * KST;                                     \
        float* _Vd = Vs + (S) * 64 * VST;                                     \
        _Pragma("unroll")                                                     \
        for (int _i = 0; _i < 4; _i++) {                                      \
            int _idx = tid + _i * 256;                                        \
            int _r = _idx >> 4;                                               \
            int _d4 = (_idx & 15) * 4;                                        \
            bool _ok = (_k0 + _r) < SEQ;                                      \
            cp16(_Kd + _r * KST + _d4, Kg + (size_t)(_k0 + _r) * HDIM + _d4, _ok); \
            cp16(_Vd + _r * VST + _d4, Vg + (size_t)(_k0 + _r) * HDIM + _d4, _ok); \
        }                                                                     \
        CP_COMMIT();                                                          \
    } while (0)

    float o[8][4];
#pragma unroll
    for (int od = 0; od < 8; od++)
#pragma unroll
        for (int i = 0; i < 4; i++) o[od][i] = 0.f;
    float m0v = -INFINITY, m1v = -INFINITY, l0 = 0.f, l1 = 0.f;

    int row0 = wm * 16 + lr;
    int row1 = row0 + 8;

    A_ISSUE(0, 0);

    for (int t = 0; t < NT; t++) {
        CP_WAIT0();
        __syncthreads();
        if (t + 1 < NT) A_ISSUE(t + 1, (t + 1) & 1);

        const float* Ksb = Ks + (t & 1) * 64 * KST;
        const float* Vsb = Vs + (t & 1) * 64 * VST;
        int k0 = t * 64;

        // S(16x32) = Q @ K^T over this warp's k-cols (logits in log2 units)
        float s[4][4];
#pragma unroll
        for (int nt = 0; nt < 4; nt++)
#pragma unroll
            for (int i = 0; i < 4; i++) s[nt][i] = 0.f;

#pragma unroll
        for (int ks = 0; ks < 8; ks++) {
            int kk = ks * 8;
            int qr = wm * 16 + lr;
            unsigned a0 = fu(Qs[qr * QST + kk + lc]);
            unsigned a1 = fu(Qs[(qr + 8) * QST + kk + lc]);
            unsigned a2 = fu(Qs[qr * QST + kk + lc + 4]);
            unsigned a3 = fu(Qs[(qr + 8) * QST + kk + lc + 4]);
#pragma unroll
            for (int nt = 0; nt < 4; nt++) {
                int krow = wn * 32 + nt * 8 + lr;
                unsigned b0 = fu(Ksb[krow * KST + kk + lc]);
                unsigned b1 = fu(Ksb[krow * KST + kk + lc + 4]);
                mma_tf32(s[nt], a0, a1, a2, a3, b0, b1);
            }
        }

        // Mask + warp-local row max (quad shuffles), per wn-half
        float rmax0 = -INFINITY, rmax1 = -INFINITY;
#pragma unroll
        for (int nt = 0; nt < 4; nt++) {
#pragma unroll
            for (int e = 0; e < 2; e++) {
                int col = k0 + wn * 32 + nt * 8 + 2 * lc + e;
                if (col >= SEQ) { s[nt][e] = -INFINITY; s[nt][2 + e] = -INFINITY; }
                rmax0 = fmaxf(rmax0, s[nt][e]);
                rmax1 = fmaxf(rmax1, s[nt][2 + e]);
            }
        }
        rmax0 = fmaxf(rmax0, __shfl_xor_sync(0xffffffffu, rmax0, 1));
        rmax0 = fmaxf(rmax0, __shfl_xor_sync(0xffffffffu, rmax0, 2));
        rmax1 = fmaxf(rmax1, __shfl_xor_sync(0xffffffffu, rmax1, 1));
        rmax1 = fmaxf(rmax1, __shfl_xor_sync(0xffffffffu, rmax1, 2));

        float mn0 = fmaxf(m0v, rmax0);
        float mn1 = fmaxf(m1v, rmax1);
        float alpha0 = ex2(m0v - mn0);
        float alpha1 = ex2(m1v - mn1);
        m0v = mn0; m1v = mn1;

        float sum0 = 0.f, sum1 = 0.f;
#pragma unroll
        for (int nt = 0; nt < 4; nt++) {
#pragma unroll
            for (int e = 0; e < 2; e++) {
                float p0 = ex2(s[nt][e] - mn0);
                float p1 = ex2(s[nt][2 + e] - mn1);
                sum0 += p0; sum1 += p1;
                s[nt][e] = to_tf32(p0);
                s[nt][2 + e] = to_tf32(p1);
            }
        }
        sum0 += __shfl_xor_sync(0xffffffffu, sum0, 1);
        sum0 += __shfl_xor_sync(0xffffffffu, sum0, 2);
        sum1 += __shfl_xor_sync(0xffffffffu, sum1, 1);
        sum1 += __shfl_xor_sync(0xffffffffu, sum1, 2);
        l0 = l0 * alpha0 + sum0;
        l1 = l1 * alpha1 + sum1;

#pragma unroll
        for (int od = 0; od < 8; od++) {
            o[od][0] *= alpha0; o[od][1] *= alpha0;
            o[od][2] *= alpha1; o[od][3] *= alpha1;
        }

        // PV over this warp's 32 k-cols: transpose P via shuffles, MMA vs V
        int srcA = lr * 4 + (lc >> 1);
        int srcB = srcA + 2;
        bool odd = lc & 1;
#pragma unroll
        for (int kb = 0; kb < 4; kb++) {
            float s0 = __shfl_sync(0xffffffffu, s[kb][0], srcA);
            float s1 = __shfl_sync(0xffffffffu, s[kb][1], srcA);
            float s2 = __shfl_sync(0xffffffffu, s[kb][2], srcA);
            float s3 = __shfl_sync(0xffffffffu, s[kb][3], srcA);
            float t0 = __shfl_sync(0xffffffffu, s[kb][0], srcB);
            float t1 = __shfl_sync(0xffffffffu, s[kb][1], srcB);
            float t2 = __shfl_sync(0xffffffffu, s[kb][2], srcB);
            float t3 = __shfl_sync(0xffffffffu, s[kb][3], srcB);
            unsigned a0 = fu(odd ? s1 : s0);
            unsigned a1 = fu(odd ? s3 : s2);
            unsigned a2 = fu(odd ? t1 : t0);
            unsigned a3 = fu(odd ? t3 : t2);
            int kbase = wn * 32 + kb * 8;
#pragma unroll
            for (int od = 0; od < 8; od++) {
                unsigned b0 = fu(Vsb[(kbase + lc) * VST + od * 8 + lr]);
                unsigned b1 = fu(Vsb[(kbase + lc + 4) * VST + od * 8 + lr]);
                mma_tf32(o[od], a0, a1, a2, a3, b0, b1);
            }
        }
    }

    // ---- Epilogue: merge the two wn halves (split-softmax combine) ----
    __syncthreads();
    if (lc == 0) {
        m_sh[wn * 64 + row0] = m0v;
        m_sh[wn * 64 + row1] = m1v;
        l_sh[wn * 64 + row0] = l0;
        l_sh[wn * 64 + row1] = l1;
    }
    __syncthreads();
    float Ma0 = m_sh[row0], Mb0 = m_sh[64 + row0];
    float Ma1 = m_sh[row1], Mb1 = m_sh[64 + row1];
    float M0 = fmaxf(Ma0, Mb0), M1 = fmaxf(Ma1, Mb1);
    float L0 = l_sh[row0] * ex2(Ma0 - M0) + l_sh[64 + row0] * ex2(Mb0 - M0);
    float L1 = l_sh[row1] * ex2(Ma1 - M1) + l_sh[64 + row1] * ex2(Mb1 - M1);
    float f0 = ex2(m0v - M0);
    float f1 = ex2(m1v - M1);

    float* Stage = Ks;
    if (wn == 0) {
#pragma unroll
        for (int od = 0; od < 8; od++) {
            *(float2*)&Stage[row0 * KST + od * 8 + lc * 2] =
                make_float2(o[od][0] * f0, o[od][1] * f0);
            *(float2*)&Stage[row1 * KST + od * 8 + lc * 2] =
                make_float2(o[od][2] * f1, o[od][3] * f1);
        }
    }
    __syncthreads();
    if (wn == 1) {
        float inv0 = 1.f / L0;
        float inv1 = 1.f / L1;
        int r0 = q0 + row0, r1 = q0 + row1;
#pragma unroll
        for (int od = 0; od < 8; od++) {
            int col = h * HDIM + od * 8 + lc * 2;
            float2 p0 = *(float2*)&Stage[row0 * KST + od * 8 + lc * 2];
            float2 p1 = *(float2*)&Stage[row1 * KST + od * 8 + lc * 2];
            if (r0 < SEQ)
                *(float2*)&g_ctx[((size_t)(b * SEQ + r0)) * DIM + col] =
                    make_float2(to_tf32((o[od][0] * f0 + p0.x) * inv0),
                                to_tf32((o[od][1] * f0 + p0.y) * inv0));
            if (r1 < SEQ)
                *(float2*)&g_ctx[((size_t)(b * SEQ + r1)) * DIM + col] =
                    make_float2(to_tf32((o[od][2] * f1 + p1.x) * inv1),
                                to_tf32((o[od][3] * f1 + p1.y) * inv1));
        }
    }
}

// ---------------------------------------------------------------------------
extern "C" void kernel_launch(void* const* d_in, const int* in_sizes, int n_in,
                              void* d_out, int out_size)
{
    const float* x  = (const float*)d_in[0];
    const float* Wq = (const float*)d_in[1];
    const float* bq = (const float*)d_in[2];
    const float* Wk = (const float*)d_in[3];
    const float* bk = (const float*)d_in[4];
    const float* Wv = (const float*)d_in[5];
    const float* bv = (const float*)d_in[6];
    const float* Wo = (const float*)d_in[7];
    const float* bo = (const float*)d_in[8];
    float* out = (float*)d_out;

    round_x<<<(MROWS * DIM / 4 + 255) / 256, 256>>>(x);
    round_w<<<(4 * DIM * DIM / 4 + 255) / 256, 256>>>(Wq, Wk, Wv, Wo);

    int gsm = (3 * ASTG + 3 * BSTG) * sizeof(float);   // 107520
    cudaFuncSetAttribute(gemm_tf32, cudaFuncAttributeMaxDynamicSharedMemorySize, gsm);

    dim3 qkvGrid((MROWS + 127) / 128, DIM / 128, 3);  // 86 x 8 x 3
    gemm_tf32<<<qkvGrid, 256, gsm>>>(bq, bk, bv, nullptr, 0);

    int asm_ = (64 * QST + 2 * 64 * KST + 2 * 64 * VST + 256) * sizeof(float);  // 90112
    cudaFuncSetAttribute(attn_tf32, cudaFuncAttributeMaxDynamicSharedMemorySize, asm_);
    dim3 attnGrid((SEQ + 63) / 64, BATCH * HEADS);  // 22 x 128
    attn_tf32<<<attnGrid, 256, asm_>>>();

    dim3 oGrid((MROWS + 127) / 128, DIM / 128, 1);
    gemm_tf32<<<oGrid, 256, gsm>>>(bo, nullptr, nullptr, out, 1);
}

// round 10
// speedup vs baseline: 1.8416x; 1.0638x over previous
#include <cuda_runtime.h>
#include <math.h>
#include <stdint.h>

#define BATCH 8
#define SEQ 1370
#define DIM 1024
#define HEADS 16
#define HDIM 64
#define MROWS (BATCH * SEQ)   // 10960

// Q pre-scale: 1/sqrt(64) * log2(e)  (softmax computed in base-2 domain)
#define QSCALE 0.18033688011112042f

// Scratch (allocation-free: device globals)
__device__ __align__(256) float g_q[BATCH * HEADS * SEQ * HDIM];   // [B,H,S,Dh] tf32, pre-scaled
__device__ __align__(256) float g_k[BATCH * HEADS * SEQ * HDIM];
__device__ __align__(256) float g_v[BATCH * HEADS * SEQ * HDIM];
__device__ __align__(256) float g_ctx[BATCH * SEQ * DIM];          // [B,S,D] tf32
__device__ __align__(256) float g_xr[MROWS * DIM];                 // x rounded to tf32
__device__ __align__(256) float g_wr[4 * DIM * DIM];               // Wq,Wk,Wv,Wo rounded [k][n]

__device__ __forceinline__ float to_tf32(float x) {
    float r; asm("cvt.rna.tf32.f32 %0, %1;" : "=f"(r) : "f"(x)); return r;
}
__device__ __forceinline__ unsigned fu(float x) { return __float_as_uint(x); }
__device__ __forceinline__ float ex2(float x) {
    float r; asm("ex2.approx.f32 %0, %1;" : "=f"(r) : "f"(x)); return r;
}

__device__ __forceinline__ void mma_tf32(float c[4],
    unsigned a0, unsigned a1, unsigned a2, unsigned a3,
    unsigned b0, unsigned b1)
{
    asm volatile(
        "mma.sync.aligned.m16n8k8.row.col.f32.tf32.tf32.f32 "
        "{%0,%1,%2,%3}, {%4,%5,%6,%7}, {%8,%9}, {%0,%1,%2,%3};"
        : "+f"(c[0]), "+f"(c[1]), "+f"(c[2]), "+f"(c[3])
        : "r"(a0), "r"(a1), "r"(a2), "r"(a3), "r"(b0), "r"(b1));
}

// ---- cp.async helpers ----
__device__ __forceinline__ void cp16(void* smem_dst, const void* gsrc, bool pred) {
    unsigned d = (unsigned)__cvta_generic_to_shared(smem_dst);
    int sz = pred ? 16 : 0;
    asm volatile("cp.async.cg.shared.global [%0], [%1], 16, %2;\n"
                 :: "r"(d), "l"(gsrc), "r"(sz));
}
#define CP_COMMIT() asm volatile("cp.async.commit_group;\n")
#define CP_WAIT0()  asm volatile("cp.async.wait_group 0;\n" ::: "memory")
#define CP_WAIT1()  asm volatile("cp.async.wait_group 1;\n" ::: "memory")

// ---------------------------------------------------------------------------
// Pre-rounding passes
// ---------------------------------------------------------------------------
__global__ __launch_bounds__(256) void round_x(const float* __restrict__ x)
{
    int i = blockIdx.x * blockDim.x + threadIdx.x;
    if (i >= MROWS * DIM / 4) return;
    float4 v = ((const float4*)x)[i];
    ((float4*)g_xr)[i] = make_float4(to_tf32(v.x), to_tf32(v.y), to_tf32(v.z), to_tf32(v.w));
}

__global__ __launch_bounds__(256) void round_w(
    const float* __restrict__ wq, const float* __restrict__ wk,
    const float* __restrict__ wv, const float* __restrict__ wo)
{
    int i = blockIdx.x * blockDim.x + threadIdx.x;
    int w = i >> 18;
    int j = i & 262143;
    const float* s = (w == 0) ? wq : (w == 1) ? wk : (w == 2) ? wv : wo;
    float4 v = ((const float4*)s)[j];
    ((float4*)g_wr)[i] = make_float4(to_tf32(v.x), to_tf32(v.y), to_tf32(v.z), to_tf32(v.w));
}

// ---------------------------------------------------------------------------
// TF32 GEMM, 3-stage cp.async pipeline (R8 proven). C = A @ W + bias.
// 128x128 tile, BK=32, 8 warps (2x4), warp tile 64x32.
// ---------------------------------------------------------------------------
#define GAST 36
#define GBST 136
#define ASTG (128 * GAST)
#define BSTG (32 * GBST)

__device__ __forceinline__ void store_pair(int csel, float* __restrict__ Cext,
                                           int m, int n, float v0, float v1)
{
    if (m >= MROWS) return;
    if (csel <= 2) {
        float* dst = (csel == 0) ? g_q : (csel == 1) ? g_k : g_v;
        if (csel == 0) { v0 = to_tf32(v0 * QSCALE); v1 = to_tf32(v1 * QSCALE); }
        else           { v0 = to_tf32(v0);          v1 = to_tf32(v1); }
        int b = m / SEQ;
        int s = m - b * SEQ;
        int h = n >> 6;
        int d = n & 63;
        *(float2*)&dst[(((size_t)(b * HEADS + h)) * SEQ + s) * HDIM + d] =
            make_float2(v0, v1);
    } else {
        *(float2*)&Cext[(size_t)m * DIM + n] = make_float2(v0, v1);
    }
}

__global__ __launch_bounds__(256, 2) void gemm_tf32(
    const float* __restrict__ B0, const float* __restrict__ B1,
    const float* __restrict__ B2, float* __restrict__ Cext, int mode)
{
    extern __shared__ float smg[];
    float* As = smg;               // [3][ASTG]
    float* Bs = smg + 3 * ASTG;    // [3][BSTG]

    int z = (mode == 1) ? 3 : blockIdx.z;
    const float* A    = (mode == 1) ? g_ctx : g_xr;
    const float* W    = g_wr + (size_t)z * DIM * DIM;
    const float* bias = (mode == 1) ? B0 : (z == 0 ? B0 : (z == 1 ? B1 : B2));
    int csel          = (mode == 1) ? 3 : z;

    int tid = threadIdx.x;
    int wid = tid >> 5, lane = tid & 31;
    int wm = wid & 1, wn = wid >> 1;
    int lr = lane >> 2, lc = lane & 3;
    int m0 = blockIdx.x * 128, n0 = blockIdx.y * 128;

    float c[4][4][4];
#pragma unroll
    for (int mt = 0; mt < 4; mt++)
#pragma unroll
        for (int nt = 0; nt < 4; nt++)
#pragma unroll
            for (int i = 0; i < 4; i++) c[mt][nt][i] = 0.f;

    int arow[4], ak4[4]; bool aval[4];
#pragma unroll
    for (int i = 0; i < 4; i++) {
        int idx = tid + i * 256;
        arow[i] = idx >> 3;
        ak4[i] = (idx & 7) * 4;
        aval[i] = (m0 + arow[i]) < MROWS;
    }
    int brow0 = tid >> 5, bn4 = (tid & 31) * 4;

#define G_ISSUE(T, S)                                                           \
    do {                                                                        \
        int _k0 = (T) * 32;                                                     \
        float* _Asd = As + (S) * ASTG;                                          \
        float* _Bsd = Bs + (S) * BSTG;                                          \
        _Pragma("unroll")                                                       \
        for (int _i = 0; _i < 4; _i++)                                          \
            cp16(_Asd + arow[_i] * GAST + ak4[_i],                              \
                 A + (size_t)(m0 + arow[_i]) * DIM + _k0 + ak4[_i], aval[_i]);  \
        _Pragma("unroll")                                                       \
        for (int _i = 0; _i < 4; _i++)                                          \
            cp16(_Bsd + (brow0 + 8 * _i) * GBST + bn4,                          \
                 W + (size_t)(_k0 + brow0 + 8 * _i) * DIM + n0 + bn4, true);    \
        CP_COMMIT();                                                            \
    } while (0)

    G_ISSUE(0, 0);
    G_ISSUE(1, 1);

    int st = 0;
    for (int t = 0; t < 32; t++) {
        if (t + 2 < 32) CP_WAIT1(); else CP_WAIT0();
        __syncthreads();
        if (t + 2 < 32) {
            int s2 = st + 2; if (s2 >= 3) s2 -= 3;
            G_ISSUE(t + 2, s2);
        }

        const float* Asb = As + st * ASTG;
        const float* Bsb = Bs + st * BSTG;

#pragma unroll
        for (int ks = 0; ks < 4; ks++) {
            int kk = ks * 8;
            unsigned bf[4][2];
#pragma unroll
            for (int nt = 0; nt < 4; nt++) {
                int col = wn * 32 + nt * 8 + lr;
                bf[nt][0] = fu(Bsb[(kk + lc) * GBST + col]);
                bf[nt][1] = fu(Bsb[(kk + lc + 4) * GBST + col]);
            }
#pragma unroll
            for (int mt = 0; mt < 4; mt++) {
                int ar = wm * 64 + mt * 16 + lr;
                unsigned a0 = fu(Asb[ar * GAST + kk + lc]);
                unsigned a1 = fu(Asb[(ar + 8) * GAST + kk + lc]);
                unsigned a2 = fu(Asb[ar * GAST + kk + lc + 4]);
                unsigned a3 = fu(Asb[(ar + 8) * GAST + kk + lc + 4]);
#pragma unroll
                for (int nt = 0; nt < 4; nt++)
                    mma_tf32(c[mt][nt], a0, a1, a2, a3, bf[nt][0], bf[nt][1]);
            }
        }
        if (++st == 3) st = 0;
    }

#pragma unroll
    for (int mt = 0; mt < 4; mt++) {
        int r0 = m0 + wm * 64 + mt * 16 + lr;
        int r1 = r0 + 8;
#pragma unroll
        for (int nt = 0; nt < 4; nt++) {
            int n = n0 + wn * 32 + nt * 8 + lc * 2;
            float b0v = bias[n], b1v = bias[n + 1];
            store_pair(csel, Cext, r0, n, c[mt][nt][0] + b0v, c[mt][nt][1] + b1v);
            store_pair(csel, Cext, r1, n, c[mt][nt][2] + b0v, c[mt][nt][3] + b1v);
        }
    }
}

// ---------------------------------------------------------------------------
// TF32 flash attention v2: 128 q-rows/CTA, 8 warps, each warp owns 16 FULL
// rows (warp tile 16x64). In-warp softmax (quad shuffles) — no cross-warp
// merge, no m/l smem. cp.async 2-stage K/V shared by all 128 rows.
// Masking only on the final partial tile.
// ---------------------------------------------------------------------------
#define QST 68
#define KST 68
#define VST 72
#define NT  ((SEQ + 63) / 64)   // 22

__global__ __launch_bounds__(256, 2) void attn_tf32()
{
    extern __shared__ float sma[];
    float* Qs = sma;                     // [128][68]
    float* Ks = Qs + 128 * QST;          // [2][64][68]
    float* Vs = Ks + 2 * 64 * KST;       // [2][64][72]

    int tid = threadIdx.x;
    int w = tid >> 5, lane = tid & 31;
    int lr = lane >> 2, lc = lane & 3;

    int bh = blockIdx.y;
    int b = bh >> 4;
    int h = bh & 15;
    int q0 = blockIdx.x * 128;

    const float* Qg = g_q + ((size_t)(b * HEADS + h)) * SEQ * HDIM;
    const float* Kg = g_k + ((size_t)(b * HEADS + h)) * SEQ * HDIM;
    const float* Vg = g_v + ((size_t)(b * HEADS + h)) * SEQ * HDIM;

    const float4 z4 = make_float4(0.f, 0.f, 0.f, 0.f);

    // Q tile: 128 rows (already tf32 + pre-scaled by 0.125*log2e)
    for (int e = tid; e < 2048; e += 256) {
        int r = e >> 4;
        int d4 = (e & 15) * 4;
        float4 v = (q0 + r < SEQ) ? *(const float4*)(Qg + (size_t)(q0 + r) * HDIM + d4) : z4;
        *(float4*)&Qs[r * QST + d4] = v;
    }

#define A_ISSUE(T, S)                                                         \
    do {                                                                      \
        int _k0 = (T) * 64;                                                   \
        float* _Kd = Ks + (S) * 64 * KST;                                     \
        float* _Vd = Vs + (S) * 64 * VST;                                     \
        _Pragma("unroll")                                                     \
        for (int _i = 0; _i < 4; _i++) {                                      \
            int _idx = tid + _i * 256;                                        \
            int _r = _idx >> 4;                                               \
            int _d4 = (_idx & 15) * 4;                                        \
            bool _ok = (_k0 + _r) < SEQ;                                      \
            cp16(_Kd + _r * KST + _d4, Kg + (size_t)(_k0 + _r) * HDIM + _d4, _ok); \
            cp16(_Vd + _r * VST + _d4, Vg + (size_t)(_k0 + _r) * HDIM + _d4, _ok); \
        }                                                                     \
        CP_COMMIT();                                                          \
    } while (0)

    float o[8][4];   // O: 16 rows x 64 d-cols per warp
#pragma unroll
    for (int od = 0; od < 8; od++)
#pragma unroll
        for (int i = 0; i < 4; i++) o[od][i] = 0.f;
    float m0v = -INFINITY, m1v = -INFINITY, l0 = 0.f, l1 = 0.f;

    int qr = w * 16 + lr;   // local q row (this warp)

    A_ISSUE(0, 0);

    for (int t = 0; t < NT; t++) {
        CP_WAIT0();
        __syncthreads();
        if (t + 1 < NT) A_ISSUE(t + 1, (t + 1) & 1);

        const float* Ksb = Ks + (t & 1) * 64 * KST;
        const float* Vsb = Vs + (t & 1) * 64 * VST;

        // S(16x64) = Q @ K^T  (full 64 k-cols per warp)
        float s[8][4];
#pragma unroll
        for (int nt = 0; nt < 8; nt++)
#pragma unroll
            for (int i = 0; i < 4; i++) s[nt][i] = 0.f;

#pragma unroll
        for (int ks = 0; ks < 8; ks++) {
            int kk = ks * 8;
            unsigned a0 = fu(Qs[qr * QST + kk + lc]);
            unsigned a1 = fu(Qs[(qr + 8) * QST + kk + lc]);
            unsigned a2 = fu(Qs[qr * QST + kk + lc + 4]);
            unsigned a3 = fu(Qs[(qr + 8) * QST + kk + lc + 4]);
#pragma unroll
            for (int nt = 0; nt < 8; nt++) {
                int krow = nt * 8 + lr;
                unsigned b0 = fu(Ksb[krow * KST + kk + lc]);
                unsigned b1 = fu(Ksb[krow * KST + kk + lc + 4]);
                mma_tf32(s[nt], a0, a1, a2, a3, b0, b1);
            }
        }

        // Mask only on the final partial tile
        if (t == NT - 1) {
#pragma unroll
            for (int nt = 0; nt < 8; nt++)
#pragma unroll
                for (int e = 0; e < 2; e++) {
                    int col = t * 64 + nt * 8 + 2 * lc + e;
                    if (col >= SEQ) { s[nt][e] = -INFINITY; s[nt][2 + e] = -INFINITY; }
                }
        }

        // In-warp row max (quad shuffles complete the 64-col row)
        float rmax0 = -INFINITY, rmax1 = -INFINITY;
#pragma unroll
        for (int nt = 0; nt < 8; nt++) {
            rmax0 = fmaxf(rmax0, fmaxf(s[nt][0], s[nt][1]));
            rmax1 = fmaxf(rmax1, fmaxf(s[nt][2], s[nt][3]));
        }
        rmax0 = fmaxf(rmax0, __shfl_xor_sync(0xffffffffu, rmax0, 1));
        rmax0 = fmaxf(rmax0, __shfl_xor_sync(0xffffffffu, rmax0, 2));
        rmax1 = fmaxf(rmax1, __shfl_xor_sync(0xffffffffu, rmax1, 1));
        rmax1 = fmaxf(rmax1, __shfl_xor_sync(0xffffffffu, rmax1, 2));

        float mn0 = fmaxf(m0v, rmax0);
        float mn1 = fmaxf(m1v, rmax1);
        float alpha0 = ex2(m0v - mn0);
        float alpha1 = ex2(m1v - mn1);
        m0v = mn0; m1v = mn1;

        float sum0 = 0.f, sum1 = 0.f;
#pragma unroll
        for (int nt = 0; nt < 8; nt++) {
#pragma unroll
            for (int e = 0; e < 2; e++) {
                float p0 = ex2(s[nt][e] - mn0);
                float p1 = ex2(s[nt][2 + e] - mn1);
                sum0 += p0; sum1 += p1;
                s[nt][e] = to_tf32(p0);
                s[nt][2 + e] = to_tf32(p1);
            }
        }
        sum0 += __shfl_xor_sync(0xffffffffu, sum0, 1);
        sum0 += __shfl_xor_sync(0xffffffffu, sum0, 2);
        sum1 += __shfl_xor_sync(0xffffffffu, sum1, 1);
        sum1 += __shfl_xor_sync(0xffffffffu, sum1, 2);
        l0 = l0 * alpha0 + sum0;
        l1 = l1 * alpha1 + sum1;

#pragma unroll
        for (int od = 0; od < 8; od++) {
            o[od][0] *= alpha0; o[od][1] *= alpha0;
            o[od][2] *= alpha1; o[od][3] *= alpha1;
        }

        // PV over all 64 k-cols: transpose P C-frag -> A-frag via shuffles
        int srcA = lr * 4 + (lc >> 1);
        int srcB = srcA + 2;
        bool odd = lc & 1;
#pragma unroll
        for (int kb = 0; kb < 8; kb++) {
            float s0 = __shfl_sync(0xffffffffu, s[kb][0], srcA);
            float s1 = __shfl_sync(0xffffffffu, s[kb][1], srcA);
            float s2 = __shfl_sync(0xffffffffu, s[kb][2], srcA);
            float s3 = __shfl_sync(0xffffffffu, s[kb][3], srcA);
            float t0 = __shfl_sync(0xffffffffu, s[kb][0], srcB);
            float t1 = __shfl_sync(0xffffffffu, s[kb][1], srcB);
            float t2 = __shfl_sync(0xffffffffu, s[kb][2], srcB);
            float t3 = __shfl_sync(0xffffffffu, s[kb][3], srcB);
            unsigned a0 = fu(odd ? s1 : s0);
            unsigned a1 = fu(odd ? s3 : s2);
            unsigned a2 = fu(odd ? t1 : t0);
            unsigned a3 = fu(odd ? t3 : t2);
            int kbase = kb * 8;
#pragma unroll
            for (int od = 0; od < 8; od++) {
                unsigned b0 = fu(Vsb[(kbase + lc) * VST + od * 8 + lr]);
                unsigned b1 = fu(Vsb[(kbase + lc + 4) * VST + od * 8 + lr]);
                mma_tf32(o[od], a0, a1, a2, a3, b0, b1);
            }
        }
    }

    // Epilogue: normalize, write [B,S,D] (tf32 for the O-proj cp.async path)
    float inv0 = 1.f / l0;
    float inv1 = 1.f / l1;
    int r0 = q0 + qr, r1 = r0 + 8;
#pragma unroll
    for (int od = 0; od < 8; od++) {
        int col = h * HDIM + od * 8 + lc * 2;
        if (r0 < SEQ)
            *(float2*)&g_ctx[((size_t)(b * SEQ + r0)) * DIM + col] =
                make_float2(to_tf32(o[od][0] * inv0), to_tf32(o[od][1] * inv0));
        if (r1 < SEQ)
            *(float2*)&g_ctx[((size_t)(b * SEQ + r1)) * DIM + col] =
                make_float2(to_tf32(o[od][2] * inv1), to_tf32(o[od][3] * inv1));
    }
}

// ---------------------------------------------------------------------------
extern "C" void kernel_launch(void* const* d_in, const int* in_sizes, int n_in,
                              void* d_out, int out_size)
{
    const float* x  = (const float*)d_in[0];
    const float* Wq = (const float*)d_in[1];
    const float* bq = (const float*)d_in[2];
    const float* Wk = (const float*)d_in[3];
    const float* bk = (const float*)d_in[4];
    const float* Wv = (const float*)d_in[5];
    const float* bv = (const float*)d_in[6];
    const float* Wo = (const float*)d_in[7];
    const float* bo = (const float*)d_in[8];
    float* out = (float*)d_out;

    round_x<<<(MROWS * DIM / 4 + 255) / 256, 256>>>(x);
    round_w<<<(4 * DIM * DIM / 4 + 255) / 256, 256>>>(Wq, Wk, Wv, Wo);

    int gsm = (3 * ASTG + 3 * BSTG) * sizeof(float);   // 107520
    cudaFuncSetAttribute(gemm_tf32, cudaFuncAttributeMaxDynamicSharedMemorySize, gsm);

    dim3 qkvGrid((MROWS + 127) / 128, DIM / 128, 3);  // 86 x 8 x 3
    gemm_tf32<<<qkvGrid, 256, gsm>>>(bq, bk, bv, nullptr, 0);

    int asm_ = (128 * QST + 2 * 64 * KST + 2 * 64 * VST) * sizeof(float);  // 106496
    cudaFuncSetAttribute(attn_tf32, cudaFuncAttributeMaxDynamicSharedMemorySize, asm_);
    dim3 attnGrid((SEQ + 127) / 128, BATCH * HEADS);  // 11 x 128
    attn_tf32<<<attnGrid, 256, asm_>>>();

    dim3 oGrid((MROWS + 127) / 128, DIM / 128, 1);
    gemm_tf32<<<oGrid, 256, gsm>>>(bo, nullptr, nullptr, out, 1);
}